// round 11
// baseline (speedup 1.0000x reference)
#include <cuda_runtime.h>
#include <cstdint>

// ---------------- problem constants (fixed by the dataset) ----------------
#define N_SRC0 60000
#define N_DST0 30000
#define E0     480000
#define N_SRC1 30000
#define N_DST1 8000
#define E1     128000
#define IMG_D  1024
#define BLK_D  768
#define FUSEDD 512
#define HEADS  8
#define HID    64
#define OUT_D  128

// ---------------- device scratch (static: no runtime allocation) ----------
__device__ float g_fi[(size_t)N_SRC0 * FUSEDD];
__device__ float g_ti[(size_t)N_SRC0 * FUSEDD];
__device__ float g_c [(size_t)N_SRC0 * FUSEDD];
__device__ float g_wT[FUSEDD * FUSEDD];           // transposed+rounded Wv / We
__device__ float g_wBig[FUSEDD * IMG_D];          // rounded W_img / W_blk / fc1 / fc2

__device__ float g_ssrc0[N_SRC0 * HEADS], g_sdst0[N_SRC0 * HEADS];
__device__ float g_den0[N_DST0 * HEADS];
__device__ float g_w0[(size_t)E0 * HEADS];
__device__ int   g_cnt0[N_DST0], g_off0[N_DST0 + 1], g_cur0[N_DST0], g_sorted0[E0];

__device__ float g_ssrc1[N_SRC1], g_sdst1[N_SRC1];
__device__ float g_den1[N_DST1];
__device__ float g_w1[E1];
__device__ int   g_cnt1[N_DST1], g_off1[N_DST1 + 1], g_cur1[N_DST1], g_sorted1[E1];

// ---------------- tf32 helpers ----------------
__device__ __forceinline__ uint32_t f2tf32(float x) {
    uint32_t r;
    asm("cvt.rna.tf32.f32 %0, %1;" : "=r"(r) : "f"(x));
    return r;
}
__device__ __forceinline__ float roundtf(float x) {
    return __uint_as_float(f2tf32(x));
}

__device__ __forceinline__ void mma_tf32(float* d, uint32_t a0, uint32_t a1,
                                         uint32_t a2, uint32_t a3,
                                         uint32_t b0, uint32_t b1) {
    asm volatile(
        "mma.sync.aligned.m16n8k8.row.col.f32.tf32.tf32.f32 "
        "{%0,%1,%2,%3}, {%4,%5,%6,%7}, {%8,%9}, {%0,%1,%2,%3};\n"
        : "+f"(d[0]), "+f"(d[1]), "+f"(d[2]), "+f"(d[3])
        : "r"(a0), "r"(a1), "r"(a2), "r"(a3), "r"(b0), "r"(b1));
}

__device__ __forceinline__ float sigmoidf_(float x) {
    return 1.f / (1.f + __expf(-x));
}

// ---------------- tf32 tensor-core GEMM --------------------------------
// C[M,N] = A[M,K] @ B[N,K]^T, fp32 in/out, fp32 accumulate. Round-7 proven
// skeleton: runtime K, NO unroll pragma on main loop (I$!), single buffer,
// two syncs per iter, coalesced staging (f = tid + l*256, row r = f>>2,
// float4 chunk c = f&3 -> 4 lanes share a row, 64B contiguous). 128x128
// tile, BK=16, 256 threads = 8 warps 2(M)x4(N), warp 64x32.
// __launch_bounds__(256,2) pins 2 CTAs/SM (regs <= 128).
// CVTA/CVTB: convert operand to tf32 in-loop; false when pre-rounded.
// Smem row of 16 words = 4 chunks; logical chunk j holds k={j,4+j,8+j,12+j};
// physical chunk = j ^ ((r>>1)&3): STS and fragment LDS.128 conflict-free.
// gate: 0 plain, 1 C=sig(acc+b)*X, 2 C=sig(acc+b)*X+Y. C tf32-rounded.
#define BM 128
#define BN 128
#define BK 16

template <bool CVTA, bool CVTB>
__global__ __launch_bounds__(256, 2) void gemm_tc(
    const float* __restrict__ A, const float* __restrict__ B,
    float* __restrict__ C, int M, int N, int K, int gate,
    const float* __restrict__ bias, const float* __restrict__ X,
    const float* __restrict__ Y)
{
    __shared__ uint32_t As[BM * BK];
    __shared__ uint32_t Bs[BN * BK];

    const int tid  = threadIdx.x;
    const int warp = tid >> 5;
    const int lane = tid & 31;
    const int g    = lane >> 2;
    const int t4   = lane & 3;
    const int wm   = warp & 1;
    const int wn   = warp >> 1;
    const int rowBase = blockIdx.y * BM;
    const int colBase = blockIdx.x * BN;
    const int chA = ((t4 ^ ((g >> 1) & 3)) << 2);  // fragment chunk offset

    float acc[4][4][4];
#pragma unroll
    for (int i = 0; i < 4; i++)
#pragma unroll
        for (int j = 0; j < 4; j++)
#pragma unroll
            for (int r = 0; r < 4; r++) acc[i][j][r] = 0.f;

    float4 stageA[2], stageB[2];

    auto g2rA = [&](int k0) {
#pragma unroll
        for (int l = 0; l < 2; l++) {
            int f = tid + l * 256;
            int r = f >> 2, c = f & 3;
            int gr = rowBase + r;
            gr = gr < M ? gr : M - 1;
            stageA[l] = *(const float4*)(A + (size_t)gr * K + k0 + c * 4);
        }
    };
    auto g2rB = [&](int k0) {
#pragma unroll
        for (int l = 0; l < 2; l++) {
            int f = tid + l * 256;
            int r = f >> 2, c = f & 3;
            stageB[l] = *(const float4*)(B + (size_t)(colBase + r) * K + k0 + c * 4);
        }
    };
    auto r2s = [&]() {
#pragma unroll
        for (int l = 0; l < 2; l++) {
            int f = tid + l * 256;
            int r = f >> 2, c = f & 3;
            int sw = (r >> 1) & 3;
            uint32_t* pa = &As[r * BK + c];
            uint32_t* pb = &Bs[r * BK + c];
            if (CVTA) {
                pa[(0 ^ sw) * 4] = f2tf32(stageA[l].x);
                pa[(1 ^ sw) * 4] = f2tf32(stageA[l].y);
                pa[(2 ^ sw) * 4] = f2tf32(stageA[l].z);
                pa[(3 ^ sw) * 4] = f2tf32(stageA[l].w);
            } else {
                pa[(0 ^ sw) * 4] = __float_as_uint(stageA[l].x);
                pa[(1 ^ sw) * 4] = __float_as_uint(stageA[l].y);
                pa[(2 ^ sw) * 4] = __float_as_uint(stageA[l].z);
                pa[(3 ^ sw) * 4] = __float_as_uint(stageA[l].w);
            }
            if (CVTB) {
                pb[(0 ^ sw) * 4] = f2tf32(stageB[l].x);
                pb[(1 ^ sw) * 4] = f2tf32(stageB[l].y);
                pb[(2 ^ sw) * 4] = f2tf32(stageB[l].z);
                pb[(3 ^ sw) * 4] = f2tf32(stageB[l].w);
            } else {
                pb[(0 ^ sw) * 4] = __float_as_uint(stageB[l].x);
                pb[(1 ^ sw) * 4] = __float_as_uint(stageB[l].y);
                pb[(2 ^ sw) * 4] = __float_as_uint(stageB[l].z);
                pb[(3 ^ sw) * 4] = __float_as_uint(stageB[l].w);
            }
        }
    };

    g2rA(0); g2rB(0);

    for (int k0 = 0; k0 < K; k0 += BK) {
        r2s();
        __syncthreads();
        if (k0 + BK < K) { g2rA(k0 + BK); g2rB(k0 + BK); }

        uint4 bf[4];
#pragma unroll
        for (int ni = 0; ni < 4; ni++)
            bf[ni] = *(const uint4*)&Bs[(wn * 32 + ni * 8 + g) * BK + chA];

#pragma unroll
        for (int mi = 0; mi < 4; mi++) {
            int m0 = wm * 64 + mi * 16;
            uint4 lo = *(const uint4*)&As[(m0 + g) * BK + chA];
            uint4 hi = *(const uint4*)&As[(m0 + 8 + g) * BK + chA];
#pragma unroll
            for (int ni = 0; ni < 4; ni++) {
                mma_tf32(acc[mi][ni], lo.x, hi.x, lo.y, hi.y, bf[ni].x, bf[ni].y);
                mma_tf32(acc[mi][ni], lo.z, hi.z, lo.w, hi.w, bf[ni].z, bf[ni].w);
            }
        }
        __syncthreads();
    }

    // epilogue: outputs tf32-rounded (they feed later GEMMs as operands)
#pragma unroll
    for (int mi = 0; mi < 4; mi++) {
        int r0 = rowBase + wm * 64 + mi * 16 + g;
#pragma unroll
        for (int ni = 0; ni < 4; ni++) {
            int cb = colBase + wn * 32 + ni * 8 + t4 * 2;
            float* a = acc[mi][ni];
#pragma unroll
            for (int half = 0; half < 2; half++) {
                int r = r0 + half * 8;
                if (r >= M) continue;
                size_t p = (size_t)r * N + cb;
                float v0 = a[half * 2], v1 = a[half * 2 + 1];
                if (gate != 0) {
                    v0 = sigmoidf_(v0 + bias[cb])     * X[p];
                    v1 = sigmoidf_(v1 + bias[cb + 1]) * X[p + 1];
                    if (gate == 2) { v0 += Y[p]; v1 += Y[p + 1]; }
                }
                C[p] = roundtf(v0);
                C[p + 1] = roundtf(v1);
            }
        }
    }
}

// ---------------- tf32 rounding pre-pass (weights) ----------------
__global__ void round_tf32(const float4* __restrict__ in, float4* __restrict__ out, int n4)
{
    int i = blockIdx.x * blockDim.x + threadIdx.x;
    if (i >= n4) return;
    float4 v = in[i];
    v.x = roundtf(v.x); v.y = roundtf(v.y);
    v.z = roundtf(v.z); v.w = roundtf(v.w);
    out[i] = v;
}

// ---------------- 512x512 transpose (+ tf32 round) ----------------
__global__ void transpose512(const float* __restrict__ in, float* __restrict__ out)
{
    __shared__ float t[32][33];
    int x = blockIdx.x * 32 + threadIdx.x;
    int y0 = blockIdx.y * 32;
#pragma unroll
    for (int i = threadIdx.y; i < 32; i += 8)
        t[i][threadIdx.x] = in[(size_t)(y0 + i) * 512 + x];
    __syncthreads();
    int ox = blockIdx.y * 32 + threadIdx.x;
    int oy0 = blockIdx.x * 32;
#pragma unroll
    for (int i = threadIdx.y; i < 32; i += 8)
        out[(size_t)(oy0 + i) * 512 + ox] = roundtf(t[threadIdx.x][i]);
}

// ---------------- attention score reductions ----------------
__global__ void attn_scores8(const float* __restrict__ z, const float* __restrict__ a,
                             float* __restrict__ ssrc, float* __restrict__ sdst, int n)
{
    int warp = (blockIdx.x * blockDim.x + threadIdx.x) >> 5;
    int lane = threadIdx.x & 31;
    if (warp >= n * HEADS) return;
    int node = warp >> 3, h = warp & 7;
    const float* zr = z + (size_t)node * FUSEDD + h * HID;
    const float* ar = a + h * (2 * HID);
    float v0 = zr[lane], v1 = zr[lane + 32];
    float ss = v0 * ar[lane] + v1 * ar[lane + 32];
    float sd = v0 * ar[64 + lane] + v1 * ar[96 + lane];
#pragma unroll
    for (int d = 16; d; d >>= 1) {
        ss += __shfl_xor_sync(0xffffffffu, ss, d);
        sd += __shfl_xor_sync(0xffffffffu, sd, d);
    }
    if (lane == 0) { ssrc[warp] = ss; sdst[warp] = sd; }
}

__global__ void attn_scores1(const float* __restrict__ z, const float* __restrict__ a,
                             float* __restrict__ ssrc, float* __restrict__ sdst, int n)
{
    int warp = (blockIdx.x * blockDim.x + threadIdx.x) >> 5;
    int lane = threadIdx.x & 31;
    if (warp >= n) return;
    const float* zr = z + (size_t)warp * OUT_D;
    float ss = 0.f, sd = 0.f;
#pragma unroll
    for (int o = lane; o < OUT_D; o += 32) {
        float v = zr[o];
        ss += v * a[o];
        sd += v * a[OUT_D + o];
    }
#pragma unroll
    for (int d = 16; d; d >>= 1) {
        ss += __shfl_xor_sync(0xffffffffu, ss, d);
        sd += __shfl_xor_sync(0xffffffffu, sd, d);
    }
    if (lane == 0) { ssrc[warp] = ss; sdst[warp] = sd; }
}

// ---------------- per-layer init ----------------
__global__ void init_l1()
{
    int i = blockIdx.x * blockDim.x + threadIdx.x;
    if (i < N_DST0 * HEADS) g_den0[i] = 0.f;
    if (i < N_DST0) { g_cnt0[i] = 0; g_cur0[i] = 0; }
}
__global__ void init_l2()
{
    int i = blockIdx.x * blockDim.x + threadIdx.x;
    if (i < N_DST1) { g_den1[i] = 0.f; g_cnt1[i] = 0; g_cur1[i] = 0; }
}

// ---------------- edge softmax (max-free: shift-invariant, O(1) scores) ---
template <int H>
__global__ void edge_exp(const int* __restrict__ src, const int* __restrict__ dst,
                         const float* __restrict__ ssrc, const float* __restrict__ sdst,
                         float* __restrict__ w, float* __restrict__ den, int E)
{
    int i = blockIdx.x * blockDim.x + threadIdx.x;
    if (i >= E * H) return;
    int e = i / H, h = i - e * H;
    int d = dst[e];
    float v = ssrc[src[e] * H + h] + sdst[d * H + h];
    v = v > 0.f ? v : 0.01f * v;
    float ex = __expf(v);
    w[i] = ex;
    atomicAdd(&den[d * H + h], ex);
}

// ---------------- CSR build ----------------
__global__ void hist_k(const int* __restrict__ dst, int* __restrict__ cnt, int E)
{
    int i = blockIdx.x * blockDim.x + threadIdx.x;
    if (i < E) atomicAdd(&cnt[dst[i]], 1);
}

__global__ void exscan_k(const int* __restrict__ cnt, int* __restrict__ off, int n)
{
    __shared__ int sm[1024];
    int tid = threadIdx.x;
    int chunk = (n + 1023) >> 10;
    int s = tid * chunk;
    int e = s + chunk < n ? s + chunk : n;
    int sum = 0;
    for (int i = s; i < e; i++) sum += cnt[i];
    sm[tid] = sum;
    __syncthreads();
    for (int d = 1; d < 1024; d <<= 1) {
        int t = (tid >= d) ? sm[tid - d] : 0;
        __syncthreads();
        sm[tid] += t;
        __syncthreads();
    }
    int run = sm[tid] - sum;
    for (int i = s; i < e; i++) { off[i] = run; run += cnt[i]; }
    if (tid == 1023) off[n] = sm[1023];
}

__global__ void scatter_k(const int* __restrict__ dst, const int* __restrict__ off,
                          int* __restrict__ cur, int* __restrict__ sorted, int E)
{
    int i = blockIdx.x * blockDim.x + threadIdx.x;
    if (i >= E) return;
    int d = dst[i];
    int p = atomicAdd(&cur[d], 1);
    sorted[off[d] + p] = i;
}

// ---------------- aggregation ----------------
// layer 1: block per dst node; 128 threads x float4; smem-staged edge ids;
// fused ELU; output tf32-rounded (it is the A operand of the z2 GEMM).
__global__ __launch_bounds__(128) void aggregate8_elu(
    const int* __restrict__ sorted, const int* __restrict__ off,
    const int* __restrict__ esrc, const float* __restrict__ w,
    const float* __restrict__ den, const float* __restrict__ z,
    float* __restrict__ out)
{
    __shared__ int s_ed[128];
    __shared__ int s_src[128];
    int d = blockIdx.x;
    int t = threadIdx.x;
    int h = t >> 4;
    float4 acc = make_float4(0.f, 0.f, 0.f, 0.f);
    int s = off[d], e = off[d + 1];
    for (int base = s; base < e; base += 128) {
        int nch = min(128, e - base);
        __syncthreads();
        if (t < nch) {
            int ed = sorted[base + t];
            s_ed[t] = ed;
            s_src[t] = esrc[ed];
        }
        __syncthreads();
#pragma unroll 2
        for (int j = 0; j < nch; j++) {
            float alpha = w[(size_t)s_ed[j] * HEADS + h];
            float4 zv = *(const float4*)(z + (size_t)s_src[j] * FUSEDD + t * 4);
            acc.x += alpha * zv.x;
            acc.y += alpha * zv.y;
            acc.z += alpha * zv.z;
            acc.w += alpha * zv.w;
        }
    }
    float inv = 1.f / den[d * HEADS + h];
    acc.x *= inv; acc.y *= inv; acc.z *= inv; acc.w *= inv;
    acc.x = acc.x > 0.f ? acc.x : (__expf(acc.x) - 1.f);
    acc.y = acc.y > 0.f ? acc.y : (__expf(acc.y) - 1.f);
    acc.z = acc.z > 0.f ? acc.z : (__expf(acc.z) - 1.f);
    acc.w = acc.w > 0.f ? acc.w : (__expf(acc.w) - 1.f);
    acc.x = roundtf(acc.x); acc.y = roundtf(acc.y);
    acc.z = roundtf(acc.z); acc.w = roundtf(acc.w);
    *(float4*)(out + (size_t)d * FUSEDD + t * 4) = acc;
}

__global__ __launch_bounds__(128) void aggregate1(
    const int* __restrict__ sorted, const int* __restrict__ off,
    const int* __restrict__ esrc, const float* __restrict__ w,
    const float* __restrict__ den, const float* __restrict__ z,
    float* __restrict__ out)
{
    __shared__ int s_src[128];
    __shared__ float s_w[128];
    int d = blockIdx.x;
    int c = threadIdx.x;
    float acc = 0.f;
    int s = off[d], e = off[d + 1];
    for (int base = s; base < e; base += 128) {
        int nch = min(128, e - base);
        __syncthreads();
        if (c < nch) {
            int ed = sorted[base + c];
            s_src[c] = esrc[ed];
            s_w[c] = w[ed];
        }
        __syncthreads();
#pragma unroll 4
        for (int j = 0; j < nch; j++)
            acc += s_w[j] * z[(size_t)s_src[j] * OUT_D + c];
    }
    out[(size_t)d * OUT_D + c] = acc / den[d];
}

// ---------------- host launcher ----------------
extern "C" void kernel_launch(void* const* d_in, const int* in_sizes, int n_in,
                              void* d_out, int out_size)
{
    (void)in_sizes; (void)n_in; (void)out_size;
    const float* img   = (const float*)d_in[0];
    const float* blk   = (const float*)d_in[1];
    const float* W_img = (const float*)d_in[2];
    const float* W_blk = (const float*)d_in[3];
    const float* Wv    = (const float*)d_in[4];
    const float* bv    = (const float*)d_in[5];
    const float* We    = (const float*)d_in[6];
    const float* be    = (const float*)d_in[7];
    const float* fc1   = (const float*)d_in[8];
    const float* attn1 = (const float*)d_in[9];
    const float* fc2   = (const float*)d_in[10];
    const float* attn2 = (const float*)d_in[11];
    const int* e0s = (const int*)d_in[12];
    const int* e0d = (const int*)d_in[13];
    const int* e1s = (const int*)d_in[14];
    const int* e1d = (const int*)d_in[15];
    float* out = (float*)d_out;

    float *fi, *ti, *c, *wT, *wBig;
    float *ssrc0, *sdst0, *den0, *w0;
    int *cnt0, *off0, *cur0, *sorted0;
    float *ssrc1, *sdst1, *den1, *w1;
    int *cnt1, *off1, *cur1, *sorted1;
    cudaGetSymbolAddress((void**)&fi, g_fi);
    cudaGetSymbolAddress((void**)&ti, g_ti);
    cudaGetSymbolAddress((void**)&c,  g_c);
    cudaGetSymbolAddress((void**)&wT, g_wT);
    cudaGetSymbolAddress((void**)&wBig, g_wBig);
    cudaGetSymbolAddress((void**)&ssrc0, g_ssrc0);
    cudaGetSymbolAddress((void**)&sdst0, g_sdst0);
    cudaGetSymbolAddress((void**)&den0, g_den0);
    cudaGetSymbolAddress((void**)&w0, g_w0);
    cudaGetSymbolAddress((void**)&cnt0, g_cnt0);
    cudaGetSymbolAddress((void**)&off0, g_off0);
    cudaGetSymbolAddress((void**)&cur0, g_cur0);
    cudaGetSymbolAddress((void**)&sorted0, g_sorted0);
    cudaGetSymbolAddress((void**)&ssrc1, g_ssrc1);
    cudaGetSymbolAddress((void**)&sdst1, g_sdst1);
    cudaGetSymbolAddress((void**)&den1, g_den1);
    cudaGetSymbolAddress((void**)&w1, g_w1);
    cudaGetSymbolAddress((void**)&cnt1, g_cnt1);
    cudaGetSymbolAddress((void**)&off1, g_off1);
    cudaGetSymbolAddress((void**)&cur1, g_cur1);
    cudaGetSymbolAddress((void**)&sorted1, g_sorted1);

    dim3 tb(256);
    dim3 gBig(FUSEDD / BN, (N_SRC0 + BM - 1) / BM);

    // 1: projection 1 (pre-round W_img; A=img converted in-kernel)
    round_tf32<<<(FUSEDD * IMG_D / 4 + 255) / 256, tb>>>((const float4*)W_img, (float4*)wBig, FUSEDD * IMG_D / 4);
    gemm_tc<true, false><<<gBig, tb>>>(img, wBig, fi, N_SRC0, FUSEDD, IMG_D, 0, nullptr, nullptr, nullptr);

    // 2: projection 2
    round_tf32<<<(FUSEDD * BLK_D / 4 + 255) / 256, tb>>>((const float4*)W_blk, (float4*)wBig, FUSEDD * BLK_D / 4);
    gemm_tc<true, false><<<gBig, tb>>>(blk, wBig, ti, N_SRC0, FUSEDD, BLK_D, 0, nullptr, nullptr, nullptr);

    // 3: visual gate fused: c = sigmoid(fi@Wv + bv) * fi
    transpose512<<<dim3(16, 16), dim3(32, 8)>>>(Wv, wT);
    gemm_tc<false, false><<<gBig, tb>>>(fi, wT, c, N_SRC0, FUSEDD, FUSEDD, 1, bv, fi, nullptr);

    // 4: edge gate fused: c = sigmoid(ti@We + be) * ti + c  (c = fused)
    transpose512<<<dim3(16, 16), dim3(32, 8)>>>(We, wT);
    gemm_tc<false, false><<<gBig, tb>>>(ti, wT, c, N_SRC0, FUSEDD, FUSEDD, 2, be, ti, c);

    // 5: z1 = fused @ fc1^T -> ti
    round_tf32<<<(FUSEDD * FUSEDD / 4 + 255) / 256, tb>>>((const float4*)fc1, (float4*)wBig, FUSEDD * FUSEDD / 4);
    gemm_tc<false, false><<<gBig, tb>>>(c, wBig, ti, N_SRC0, FUSEDD, FUSEDD, 0, nullptr, nullptr, nullptr);

    // 6: attention scores layer 1
    attn_scores8<<<(N_SRC0 * HEADS * 32 + 255) / 256, tb>>>(ti, attn1, ssrc0, sdst0, N_SRC0);

    // 7-12: edge softmax + CSR + aggregate (layer 1), fused ELU -> fi
    init_l1<<<(N_DST0 * HEADS + 255) / 256, tb>>>();
    edge_exp<HEADS><<<(E0 * HEADS + 255) / 256, tb>>>(e0s, e0d, ssrc0, sdst0, w0, den0, E0);
    hist_k<<<(E0 + 255) / 256, tb>>>(e0d, cnt0, E0);
    exscan_k<<<1, 1024>>>(cnt0, off0, N_DST0);
    scatter_k<<<(E0 + 255) / 256, tb>>>(e0d, off0, cur0, sorted0, E0);
    aggregate8_elu<<<N_DST0, 128>>>(sorted0, off0, e0s, w0, den0, ti, fi);

    // 13: z2 = h @ fc2^T -> c
    round_tf32<<<(OUT_D * FUSEDD / 4 + 255) / 256, tb>>>((const float4*)fc2, (float4*)wBig, OUT_D * FUSEDD / 4);
    gemm_tc<false, false><<<dim3(OUT_D / BN, (N_SRC1 + BM - 1) / BM), tb>>>(fi, wBig, c, N_SRC1, OUT_D, FUSEDD, 0, nullptr, nullptr, nullptr);

    // 14-20: layer 2 edge softmax + aggregate -> d_out
    attn_scores1<<<(N_SRC1 * 32 + 255) / 256, tb>>>(c, attn2, ssrc1, sdst1, N_SRC1);
    init_l2<<<(N_DST1 + 255) / 256, tb>>>();
    edge_exp<1><<<(E1 + 255) / 256, tb>>>(e1s, e1d, ssrc1, sdst1, w1, den1, E1);
    hist_k<<<(E1 + 255) / 256, tb>>>(e1d, cnt1, E1);
    exscan_k<<<1, 1024>>>(cnt1, off1, N_DST1);
    scatter_k<<<(E1 + 255) / 256, tb>>>(e1d, off1, cur1, sorted1, E1);
    aggregate1<<<N_DST1, 128>>>(sorted1, off1, e1s, w1, den1, c, out);
}

// round 13
// speedup vs baseline: 1.3555x; 1.3555x over previous
#include <cuda_runtime.h>
#include <cstdint>

// ---------------- problem constants (fixed by the dataset) ----------------
#define N_SRC0 60000
#define N_DST0 30000
#define E0     480000
#define N_SRC1 30000
#define N_DST1 8000
#define E1     128000
#define IMG_D  1024
#define BLK_D  768
#define FUSEDD 512
#define HEADS  8
#define HID    64
#define OUT_D  128

// ---------------- device scratch (static: no runtime allocation) ----------
__device__ float g_fi[(size_t)N_SRC0 * FUSEDD];
__device__ float g_ti[(size_t)N_SRC0 * FUSEDD];
__device__ float g_c [(size_t)N_SRC0 * FUSEDD];
__device__ float g_wT[FUSEDD * FUSEDD];           // transposed+permuted+rounded Wv / We
__device__ float g_wBig[FUSEDD * IMG_D];          // permuted+rounded W_img / W_blk / fc1 / fc2

__device__ float g_ssrc0[N_SRC0 * HEADS], g_sdst0[N_SRC0 * HEADS];
__device__ float g_den0[N_DST0 * HEADS];
__device__ float g_w0[(size_t)E0 * HEADS];
__device__ int   g_cnt0[N_DST0], g_off0[N_DST0 + 1], g_cur0[N_DST0], g_sorted0[E0];

__device__ float g_ssrc1[N_SRC1], g_sdst1[N_SRC1];
__device__ float g_den1[N_DST1];
__device__ float g_w1[E1];
__device__ int   g_cnt1[N_DST1], g_off1[N_DST1 + 1], g_cur1[N_DST1], g_sorted1[E1];

// ---------------- tf32 helpers ----------------
__device__ __forceinline__ uint32_t f2tf32(float x) {
    uint32_t r;
    asm("cvt.rna.tf32.f32 %0, %1;" : "=r"(r) : "f"(x));
    return r;
}
__device__ __forceinline__ float roundtf(float x) {
    return __uint_as_float(f2tf32(x));
}

__device__ __forceinline__ void mma_tf32(float* d, uint32_t a0, uint32_t a1,
                                         uint32_t a2, uint32_t a3,
                                         uint32_t b0, uint32_t b1) {
    asm volatile(
        "mma.sync.aligned.m16n8k8.row.col.f32.tf32.tf32.f32 "
        "{%0,%1,%2,%3}, {%4,%5,%6,%7}, {%8,%9}, {%0,%1,%2,%3};\n"
        : "+f"(d[0]), "+f"(d[1]), "+f"(d[2]), "+f"(d[3])
        : "r"(a0), "r"(a1), "r"(a2), "r"(a3), "r"(b0), "r"(b1));
}

__device__ __forceinline__ float sigmoidf_(float x) {
    return 1.f / (1.f + __expf(-x));
}

// ---------------- tf32 tensor-core GEMM --------------------------------
// C[M,N] = A[M,K] @ B[N,K]^T, fp32 A/C, B pre-permuted+tf32-rounded.
// 128x128 tile, BK=16, 256 threads = 8 warps 2(M)x4(N), warp 64x32.
// A: coalesced staging through swizzled smem (R6/R7-proven): f=tid+l*256,
//    row r=f>>2, chunk c=f&3; smem chunk q = j ^ ((r>>1)&3); in-loop CVT.
// B: NO smem. Weights are stored fragment-permuted (16-group position p
//    holds k = 4*(p&3) + (p>>2)), so each thread's b-fragment {t4, t4+4,
//    t4+8, t4+12} is ONE contiguous LDG.128 from global (L2/L1-resident,
//    reused by all row-blocks). Removes 8 STS + 4 LDS.128 per warp-iter.
// Single smem buffer, two syncs/iter. gate: 0 plain, 1 C=sig(acc+b)*X,
// 2 C=sig(acc+b)*X+Y.
#define BM 128
#define BN 128
#define BK 16

__global__ __launch_bounds__(256, 2) void gemm_tc(
    const float* __restrict__ A, const float* __restrict__ Bp,
    float* __restrict__ C, int M, int N, int K, int gate,
    const float* __restrict__ bias, const float* __restrict__ X,
    const float* __restrict__ Y)
{
    __shared__ uint32_t As[BM * BK];

    const int tid  = threadIdx.x;
    const int warp = tid >> 5;
    const int lane = tid & 31;
    const int g    = lane >> 2;
    const int t4   = lane & 3;
    const int wm   = warp & 1;
    const int wn   = warp >> 1;
    const int rowBase = blockIdx.y * BM;
    const int colBase = blockIdx.x * BN;
    const int chA = ((t4 ^ ((g >> 1) & 3)) << 2);  // A fragment chunk offset

    float acc[4][4][4];
#pragma unroll
    for (int i = 0; i < 4; i++)
#pragma unroll
        for (int j = 0; j < 4; j++)
#pragma unroll
            for (int r = 0; r < 4; r++) acc[i][j][r] = 0.f;

    // B fragment row pointers (fixed per thread)
    const float* bRow[4];
#pragma unroll
    for (int ni = 0; ni < 4; ni++)
        bRow[ni] = Bp + (size_t)(colBase + wn * 32 + ni * 8 + g) * K + 4 * t4;

    float4 stageA[2];
    auto g2rA = [&](int k0) {
#pragma unroll
        for (int l = 0; l < 2; l++) {
            int f = tid + l * 256;
            int r = f >> 2, c = f & 3;
            int gr = rowBase + r;
            gr = gr < M ? gr : M - 1;
            stageA[l] = *(const float4*)(A + (size_t)gr * K + k0 + c * 4);
        }
    };
    auto r2s = [&]() {
#pragma unroll
        for (int l = 0; l < 2; l++) {
            int f = tid + l * 256;
            int r = f >> 2, c = f & 3;
            int sw = (r >> 1) & 3;
            uint32_t* pa = &As[r * BK + c];
            pa[(0 ^ sw) * 4] = f2tf32(stageA[l].x);
            pa[(1 ^ sw) * 4] = f2tf32(stageA[l].y);
            pa[(2 ^ sw) * 4] = f2tf32(stageA[l].z);
            pa[(3 ^ sw) * 4] = f2tf32(stageA[l].w);
        }
    };

    g2rA(0);

    for (int k0 = 0; k0 < K; k0 += BK) {
        r2s();
        __syncthreads();
        if (k0 + BK < K) g2rA(k0 + BK);

        // B fragments: one LDG.128 per n-tile, straight from permuted weights
        uint4 bf[4];
#pragma unroll
        for (int ni = 0; ni < 4; ni++)
            bf[ni] = *(const uint4*)(bRow[ni] + k0);

#pragma unroll
        for (int mi = 0; mi < 4; mi++) {
            int m0 = wm * 64 + mi * 16;
            uint4 lo = *(const uint4*)&As[(m0 + g) * BK + chA];
            uint4 hi = *(const uint4*)&As[(m0 + 8 + g) * BK + chA];
#pragma unroll
            for (int ni = 0; ni < 4; ni++) {
                mma_tf32(acc[mi][ni], lo.x, hi.x, lo.y, hi.y, bf[ni].x, bf[ni].y);
                mma_tf32(acc[mi][ni], lo.z, hi.z, lo.w, hi.w, bf[ni].z, bf[ni].w);
            }
        }
        __syncthreads();
    }

    // epilogue
#pragma unroll
    for (int mi = 0; mi < 4; mi++) {
        int r0 = rowBase + wm * 64 + mi * 16 + g;
#pragma unroll
        for (int ni = 0; ni < 4; ni++) {
            int cb = colBase + wn * 32 + ni * 8 + t4 * 2;
            float* a = acc[mi][ni];
#pragma unroll
            for (int half = 0; half < 2; half++) {
                int r = r0 + half * 8;
                if (r >= M) continue;
                size_t p = (size_t)r * N + cb;
                float v0 = a[half * 2], v1 = a[half * 2 + 1];
                if (gate != 0) {
                    v0 = sigmoidf_(v0 + bias[cb])     * X[p];
                    v1 = sigmoidf_(v1 + bias[cb + 1]) * X[p + 1];
                    if (gate == 2) { v0 += Y[p]; v1 += Y[p + 1]; }
                }
                C[p] = v0;
                C[p + 1] = v1;
            }
        }
    }
}

// ---------------- weight permute+round pre-pass --------------------------
// Output position p within each 16-k group holds k = 4*(p&3) + (p>>2),
// tf32-rounded. Coalesced writes; reads stay within the same 64B group.
__global__ void permute_round(const float* __restrict__ in, float* __restrict__ out, int n)
{
    int i = blockIdx.x * blockDim.x + threadIdx.x;
    if (i >= n) return;
    int p = i & 15;
    int k = (i & ~15) | (4 * (p & 3) + (p >> 2));
    out[i] = roundtf(in[k]);
}

// ---------------- 512x512 transpose (+ permute + round) ------------------
__global__ void transpose512(const float* __restrict__ in, float* __restrict__ out)
{
    __shared__ float t[32][33];
    int x = blockIdx.x * 32 + threadIdx.x;
    int y0 = blockIdx.y * 32;
#pragma unroll
    for (int i = threadIdx.y; i < 32; i += 8)
        t[i][threadIdx.x] = in[(size_t)(y0 + i) * 512 + x];
    __syncthreads();
    int ox = blockIdx.y * 32 + threadIdx.x;       // k index of the output
    int q = (ox & ~15) | ((ox & 3) * 4 + ((ox >> 2) & 3));  // permuted position
    int oy0 = blockIdx.x * 32;
#pragma unroll
    for (int i = threadIdx.y; i < 32; i += 8)
        out[(size_t)(oy0 + i) * 512 + q] = roundtf(t[threadIdx.x][i]);
}

// ---------------- attention score reductions ----------------
__global__ void attn_scores8(const float* __restrict__ z, const float* __restrict__ a,
                             float* __restrict__ ssrc, float* __restrict__ sdst, int n)
{
    int warp = (blockIdx.x * blockDim.x + threadIdx.x) >> 5;
    int lane = threadIdx.x & 31;
    if (warp >= n * HEADS) return;
    int node = warp >> 3, h = warp & 7;
    const float* zr = z + (size_t)node * FUSEDD + h * HID;
    const float* ar = a + h * (2 * HID);
    float v0 = zr[lane], v1 = zr[lane + 32];
    float ss = v0 * ar[lane] + v1 * ar[lane + 32];
    float sd = v0 * ar[64 + lane] + v1 * ar[96 + lane];
#pragma unroll
    for (int d = 16; d; d >>= 1) {
        ss += __shfl_xor_sync(0xffffffffu, ss, d);
        sd += __shfl_xor_sync(0xffffffffu, sd, d);
    }
    if (lane == 0) { ssrc[warp] = ss; sdst[warp] = sd; }
}

__global__ void attn_scores1(const float* __restrict__ z, const float* __restrict__ a,
                             float* __restrict__ ssrc, float* __restrict__ sdst, int n)
{
    int warp = (blockIdx.x * blockDim.x + threadIdx.x) >> 5;
    int lane = threadIdx.x & 31;
    if (warp >= n) return;
    const float* zr = z + (size_t)warp * OUT_D;
    float ss = 0.f, sd = 0.f;
#pragma unroll
    for (int o = lane; o < OUT_D; o += 32) {
        float v = zr[o];
        ss += v * a[o];
        sd += v * a[OUT_D + o];
    }
#pragma unroll
    for (int d = 16; d; d >>= 1) {
        ss += __shfl_xor_sync(0xffffffffu, ss, d);
        sd += __shfl_xor_sync(0xffffffffu, sd, d);
    }
    if (lane == 0) { ssrc[warp] = ss; sdst[warp] = sd; }
}

// ---------------- per-layer init ----------------
__global__ void init_l1()
{
    int i = blockIdx.x * blockDim.x + threadIdx.x;
    if (i < N_DST0 * HEADS) g_den0[i] = 0.f;
    if (i < N_DST0) { g_cnt0[i] = 0; g_cur0[i] = 0; }
}
__global__ void init_l2()
{
    int i = blockIdx.x * blockDim.x + threadIdx.x;
    if (i < N_DST1) { g_den1[i] = 0.f; g_cnt1[i] = 0; g_cur1[i] = 0; }
}

// ---------------- edge softmax (max-free: shift-invariant, O(1) scores) ---
template <int H>
__global__ void edge_exp(const int* __restrict__ src, const int* __restrict__ dst,
                         const float* __restrict__ ssrc, const float* __restrict__ sdst,
                         float* __restrict__ w, float* __restrict__ den, int E)
{
    int i = blockIdx.x * blockDim.x + threadIdx.x;
    if (i >= E * H) return;
    int e = i / H, h = i - e * H;
    int d = dst[e];
    float v = ssrc[src[e] * H + h] + sdst[d * H + h];
    v = v > 0.f ? v : 0.01f * v;
    float ex = __expf(v);
    w[i] = ex;
    atomicAdd(&den[d * H + h], ex);
}

// ---------------- CSR build ----------------
__global__ void hist_k(const int* __restrict__ dst, int* __restrict__ cnt, int E)
{
    int i = blockIdx.x * blockDim.x + threadIdx.x;
    if (i < E) atomicAdd(&cnt[dst[i]], 1);
}

__global__ void exscan_k(const int* __restrict__ cnt, int* __restrict__ off, int n)
{
    __shared__ int sm[1024];
    int tid = threadIdx.x;
    int chunk = (n + 1023) >> 10;
    int s = tid * chunk;
    int e = s + chunk < n ? s + chunk : n;
    int sum = 0;
    for (int i = s; i < e; i++) sum += cnt[i];
    sm[tid] = sum;
    __syncthreads();
    for (int d = 1; d < 1024; d <<= 1) {
        int t = (tid >= d) ? sm[tid - d] : 0;
        __syncthreads();
        sm[tid] += t;
        __syncthreads();
    }
    int run = sm[tid] - sum;
    for (int i = s; i < e; i++) { off[i] = run; run += cnt[i]; }
    if (tid == 1023) off[n] = sm[1023];
}

__global__ void scatter_k(const int* __restrict__ dst, const int* __restrict__ off,
                          int* __restrict__ cur, int* __restrict__ sorted, int E)
{
    int i = blockIdx.x * blockDim.x + threadIdx.x;
    if (i >= E) return;
    int d = dst[i];
    int p = atomicAdd(&cur[d], 1);
    sorted[off[d] + p] = i;
}

// ---------------- aggregation ----------------
// layer 1: block per dst node; 128 threads x float4; smem-staged edge ids;
// fused ELU (R7-proven).
__global__ __launch_bounds__(128) void aggregate8_elu(
    const int* __restrict__ sorted, const int* __restrict__ off,
    const int* __restrict__ esrc, const float* __restrict__ w,
    const float* __restrict__ den, const float* __restrict__ z,
    float* __restrict__ out)
{
    __shared__ int s_ed[128];
    __shared__ int s_src[128];
    int d = blockIdx.x;
    int t = threadIdx.x;
    int h = t >> 4;
    float4 acc = make_float4(0.f, 0.f, 0.f, 0.f);
    int s = off[d], e = off[d + 1];
    for (int base = s; base < e; base += 128) {
        int nch = min(128, e - base);
        __syncthreads();
        if (t < nch) {
            int ed = sorted[base + t];
            s_ed[t] = ed;
            s_src[t] = esrc[ed];
        }
        __syncthreads();
#pragma unroll 2
        for (int j = 0; j < nch; j++) {
            float alpha = w[(size_t)s_ed[j] * HEADS + h];
            float4 zv = *(const float4*)(z + (size_t)s_src[j] * FUSEDD + t * 4);
            acc.x += alpha * zv.x;
            acc.y += alpha * zv.y;
            acc.z += alpha * zv.z;
            acc.w += alpha * zv.w;
        }
    }
    float inv = 1.f / den[d * HEADS + h];
    acc.x *= inv; acc.y *= inv; acc.z *= inv; acc.w *= inv;
    acc.x = acc.x > 0.f ? acc.x : (__expf(acc.x) - 1.f);
    acc.y = acc.y > 0.f ? acc.y : (__expf(acc.y) - 1.f);
    acc.z = acc.z > 0.f ? acc.z : (__expf(acc.z) - 1.f);
    acc.w = acc.w > 0.f ? acc.w : (__expf(acc.w) - 1.f);
    *(float4*)(out + (size_t)d * FUSEDD + t * 4) = acc;
}

__global__ __launch_bounds__(128) void aggregate1(
    const int* __restrict__ sorted, const int* __restrict__ off,
    const int* __restrict__ esrc, const float* __restrict__ w,
    const float* __restrict__ den, const float* __restrict__ z,
    float* __restrict__ out)
{
    __shared__ int s_src[128];
    __shared__ float s_w[128];
    int d = blockIdx.x;
    int c = threadIdx.x;
    float acc = 0.f;
    int s = off[d], e = off[d + 1];
    for (int base = s; base < e; base += 128) {
        int nch = min(128, e - base);
        __syncthreads();
        if (c < nch) {
            int ed = sorted[base + c];
            s_src[c] = esrc[ed];
            s_w[c] = w[ed];
        }
        __syncthreads();
#pragma unroll 4
        for (int j = 0; j < nch; j++)
            acc += s_w[j] * z[(size_t)s_src[j] * OUT_D + c];
    }
    out[(size_t)d * OUT_D + c] = acc / den[d];
}

// ---------------- host launcher ----------------
extern "C" void kernel_launch(void* const* d_in, const int* in_sizes, int n_in,
                              void* d_out, int out_size)
{
    (void)in_sizes; (void)n_in; (void)out_size;
    const float* img   = (const float*)d_in[0];
    const float* blk   = (const float*)d_in[1];
    const float* W_img = (const float*)d_in[2];
    const float* W_blk = (const float*)d_in[3];
    const float* Wv    = (const float*)d_in[4];
    const float* bv    = (const float*)d_in[5];
    const float* We    = (const float*)d_in[6];
    const float* be    = (const float*)d_in[7];
    const float* fc1   = (const float*)d_in[8];
    const float* attn1 = (const float*)d_in[9];
    const float* fc2   = (const float*)d_in[10];
    const float* attn2 = (const float*)d_in[11];
    const int* e0s = (const int*)d_in[12];
    const int* e0d = (const int*)d_in[13];
    const int* e1s = (const int*)d_in[14];
    const int* e1d = (const int*)d_in[15];
    float* out = (float*)d_out;

    float *fi, *ti, *c, *wT, *wBig;
    float *ssrc0, *sdst0, *den0, *w0;
    int *cnt0, *off0, *cur0, *sorted0;
    float *ssrc1, *sdst1, *den1, *w1;
    int *cnt1, *off1, *cur1, *sorted1;
    cudaGetSymbolAddress((void**)&fi, g_fi);
    cudaGetSymbolAddress((void**)&ti, g_ti);
    cudaGetSymbolAddress((void**)&c,  g_c);
    cudaGetSymbolAddress((void**)&wT, g_wT);
    cudaGetSymbolAddress((void**)&wBig, g_wBig);
    cudaGetSymbolAddress((void**)&ssrc0, g_ssrc0);
    cudaGetSymbolAddress((void**)&sdst0, g_sdst0);
    cudaGetSymbolAddress((void**)&den0, g_den0);
    cudaGetSymbolAddress((void**)&w0, g_w0);
    cudaGetSymbolAddress((void**)&cnt0, g_cnt0);
    cudaGetSymbolAddress((void**)&off0, g_off0);
    cudaGetSymbolAddress((void**)&cur0, g_cur0);
    cudaGetSymbolAddress((void**)&sorted0, g_sorted0);
    cudaGetSymbolAddress((void**)&ssrc1, g_ssrc1);
    cudaGetSymbolAddress((void**)&sdst1, g_sdst1);
    cudaGetSymbolAddress((void**)&den1, g_den1);
    cudaGetSymbolAddress((void**)&w1, g_w1);
    cudaGetSymbolAddress((void**)&cnt1, g_cnt1);
    cudaGetSymbolAddress((void**)&off1, g_off1);
    cudaGetSymbolAddress((void**)&cur1, g_cur1);
    cudaGetSymbolAddress((void**)&sorted1, g_sorted1);

    dim3 tb(256);
    dim3 gBig(FUSEDD / BN, (N_SRC0 + BM - 1) / BM);

    // 1: projection 1 (permute+round W_img into wBig)
    permute_round<<<(FUSEDD * IMG_D + 255) / 256, tb>>>(W_img, wBig, FUSEDD * IMG_D);
    gemm_tc<<<gBig, tb>>>(img, wBig, fi, N_SRC0, FUSEDD, IMG_D, 0, nullptr, nullptr, nullptr);

    // 2: projection 2
    permute_round<<<(FUSEDD * BLK_D + 255) / 256, tb>>>(W_blk, wBig, FUSEDD * BLK_D);
    gemm_tc<<<gBig, tb>>>(blk, wBig, ti, N_SRC0, FUSEDD, BLK_D, 0, nullptr, nullptr, nullptr);

    // 3: visual gate fused: c = sigmoid(fi@Wv + bv) * fi
    transpose512<<<dim3(16, 16), dim3(32, 8)>>>(Wv, wT);
    gemm_tc<<<gBig, tb>>>(fi, wT, c, N_SRC0, FUSEDD, FUSEDD, 1, bv, fi, nullptr);

    // 4: edge gate fused: c = sigmoid(ti@We + be) * ti + c  (c = fused)
    transpose512<<<dim3(16, 16), dim3(32, 8)>>>(We, wT);
    gemm_tc<<<gBig, tb>>>(ti, wT, c, N_SRC0, FUSEDD, FUSEDD, 2, be, ti, c);

    // 5: z1 = fused @ fc1^T -> ti
    permute_round<<<(FUSEDD * FUSEDD + 255) / 256, tb>>>(fc1, wBig, FUSEDD * FUSEDD);
    gemm_tc<<<gBig, tb>>>(c, wBig, ti, N_SRC0, FUSEDD, FUSEDD, 0, nullptr, nullptr, nullptr);

    // 6: attention scores layer 1
    attn_scores8<<<(N_SRC0 * HEADS * 32 + 255) / 256, tb>>>(ti, attn1, ssrc0, sdst0, N_SRC0);

    // 7-12: edge softmax + CSR + aggregate (layer 1), fused ELU -> fi
    init_l1<<<(N_DST0 * HEADS + 255) / 256, tb>>>();
    edge_exp<HEADS><<<(E0 * HEADS + 255) / 256, tb>>>(e0s, e0d, ssrc0, sdst0, w0, den0, E0);
    hist_k<<<(E0 + 255) / 256, tb>>>(e0d, cnt0, E0);
    exscan_k<<<1, 1024>>>(cnt0, off0, N_DST0);
    scatter_k<<<(E0 + 255) / 256, tb>>>(e0d, off0, cur0, sorted0, E0);
    aggregate8_elu<<<N_DST0, 128>>>(sorted0, off0, e0s, w0, den0, ti, fi);

    // 13: z2 = h @ fc2^T -> c
    permute_round<<<(OUT_D * FUSEDD + 255) / 256, tb>>>(fc2, wBig, OUT_D * FUSEDD);
    gemm_tc<<<dim3(OUT_D / BN, (N_SRC1 + BM - 1) / BM), tb>>>(fi, wBig, c, N_SRC1, OUT_D, FUSEDD, 0, nullptr, nullptr, nullptr);

    // 14-20: layer 2 edge softmax + aggregate -> d_out
    attn_scores1<<<(N_SRC1 * 32 + 255) / 256, tb>>>(c, attn2, ssrc1, sdst1, N_SRC1);
    init_l2<<<(N_DST1 + 255) / 256, tb>>>();
    edge_exp<1><<<(E1 + 255) / 256, tb>>>(e1s, e1d, ssrc1, sdst1, w1, den1, E1);
    hist_k<<<(E1 + 255) / 256, tb>>>(e1d, cnt1, E1);
    exscan_k<<<1, 1024>>>(cnt1, off1, N_DST1);
    scatter_k<<<(E1 + 255) / 256, tb>>>(e1d, off1, cur1, sorted1, E1);
    aggregate1<<<N_DST1, 128>>>(sorted1, off1, e1s, w1, den1, c, out);
}

// round 14
// speedup vs baseline: 1.4428x; 1.0644x over previous
#include <cuda_runtime.h>
#include <cuda_fp16.h>
#include <cstdint>

// ---------------- problem constants (fixed by the dataset) ----------------
#define N_SRC0 60000
#define N_DST0 30000
#define E0     480000
#define N_SRC1 30000
#define N_DST1 8000
#define E1     128000
#define IMG_D  1024
#define BLK_D  768
#define FUSEDD 512
#define HEADS  8
#define HID    64
#define OUT_D  128

// ---------------- device scratch (static: no runtime allocation) ----------
__device__ float g_fi[(size_t)N_SRC0 * FUSEDD];
__device__ float g_ti[(size_t)N_SRC0 * FUSEDD];   // also reused as __half z1
__device__ float g_c [(size_t)N_SRC0 * FUSEDD];
__device__ float g_wT[FUSEDD * FUSEDD];           // transposed+permuted+rounded Wv / We
__device__ float g_wBig[FUSEDD * IMG_D];          // permuted+rounded weights

__device__ float g_ssrc0[N_SRC0 * HEADS], g_sdst0[N_SRC0 * HEADS];
__device__ float g_den0[N_DST0 * HEADS];
__device__ float g_w0[(size_t)E0 * HEADS];
__device__ int   g_cnt0[N_DST0], g_off0[N_DST0 + 1], g_cur0[N_DST0], g_sorted0[E0];

__device__ float g_ssrc1[N_SRC1], g_sdst1[N_SRC1];
__device__ float g_den1[N_DST1];
__device__ float g_w1[E1];
__device__ int   g_cnt1[N_DST1], g_off1[N_DST1 + 1], g_cur1[N_DST1], g_sorted1[E1];

// ---------------- tf32 helpers ----------------
__device__ __forceinline__ uint32_t f2tf32(float x) {
    uint32_t r;
    asm("cvt.rna.tf32.f32 %0, %1;" : "=r"(r) : "f"(x));
    return r;
}
__device__ __forceinline__ float roundtf(float x) {
    return __uint_as_float(f2tf32(x));
}

__device__ __forceinline__ void mma_tf32(float* d, uint32_t a0, uint32_t a1,
                                         uint32_t a2, uint32_t a3,
                                         uint32_t b0, uint32_t b1) {
    asm volatile(
        "mma.sync.aligned.m16n8k8.row.col.f32.tf32.tf32.f32 "
        "{%0,%1,%2,%3}, {%4,%5,%6,%7}, {%8,%9}, {%0,%1,%2,%3};\n"
        : "+f"(d[0]), "+f"(d[1]), "+f"(d[2]), "+f"(d[3])
        : "r"(a0), "r"(a1), "r"(a2), "r"(a3), "r"(b0), "r"(b1));
}

__device__ __forceinline__ float sigmoidf_(float x) {
    return 1.f / (1.f + __expf(-x));
}

// ---------------- tf32 tensor-core GEMM (R13-proven) --------------------
// C[M,N] = A[M,K] @ B[N,K]^T, fp32 A, B pre-permuted+tf32-rounded.
// 128x128 tile, BK=16, 8 warps 2(M)x4(N). A staged via swizzled smem with
// in-loop CVT; B fragments ONE LDG.128 each from permuted global weights.
// gate: 0 plain, 1 C=sig(acc+b)*X, 2 C=sig(acc+b)*X+Y.
// Ch != nullptr -> write __half output (half2 stores) instead of C.
#define BM 128
#define BN 128
#define BK 16

__global__ __launch_bounds__(256, 2) void gemm_tc(
    const float* __restrict__ A, const float* __restrict__ Bp,
    float* __restrict__ C, __half* __restrict__ Ch,
    int M, int N, int K, int gate,
    const float* __restrict__ bias, const float* __restrict__ X,
    const float* __restrict__ Y)
{
    __shared__ uint32_t As[BM * BK];

    const int tid  = threadIdx.x;
    const int warp = tid >> 5;
    const int lane = tid & 31;
    const int g    = lane >> 2;
    const int t4   = lane & 3;
    const int wm   = warp & 1;
    const int wn   = warp >> 1;
    const int rowBase = blockIdx.y * BM;
    const int colBase = blockIdx.x * BN;
    const int chA = ((t4 ^ ((g >> 1) & 3)) << 2);

    float acc[4][4][4];
#pragma unroll
    for (int i = 0; i < 4; i++)
#pragma unroll
        for (int j = 0; j < 4; j++)
#pragma unroll
            for (int r = 0; r < 4; r++) acc[i][j][r] = 0.f;

    const float* bRow[4];
#pragma unroll
    for (int ni = 0; ni < 4; ni++)
        bRow[ni] = Bp + (size_t)(colBase + wn * 32 + ni * 8 + g) * K + 4 * t4;

    float4 stageA[2];
    auto g2rA = [&](int k0) {
#pragma unroll
        for (int l = 0; l < 2; l++) {
            int f = tid + l * 256;
            int r = f >> 2, c = f & 3;
            int gr = rowBase + r;
            gr = gr < M ? gr : M - 1;
            stageA[l] = *(const float4*)(A + (size_t)gr * K + k0 + c * 4);
        }
    };
    auto r2s = [&]() {
#pragma unroll
        for (int l = 0; l < 2; l++) {
            int f = tid + l * 256;
            int r = f >> 2, c = f & 3;
            int sw = (r >> 1) & 3;
            uint32_t* pa = &As[r * BK + c];
            pa[(0 ^ sw) * 4] = f2tf32(stageA[l].x);
            pa[(1 ^ sw) * 4] = f2tf32(stageA[l].y);
            pa[(2 ^ sw) * 4] = f2tf32(stageA[l].z);
            pa[(3 ^ sw) * 4] = f2tf32(stageA[l].w);
        }
    };

    g2rA(0);

    for (int k0 = 0; k0 < K; k0 += BK) {
        r2s();
        __syncthreads();
        if (k0 + BK < K) g2rA(k0 + BK);

        uint4 bf[4];
#pragma unroll
        for (int ni = 0; ni < 4; ni++)
            bf[ni] = *(const uint4*)(bRow[ni] + k0);

#pragma unroll
        for (int mi = 0; mi < 4; mi++) {
            int m0 = wm * 64 + mi * 16;
            uint4 lo = *(const uint4*)&As[(m0 + g) * BK + chA];
            uint4 hi = *(const uint4*)&As[(m0 + 8 + g) * BK + chA];
#pragma unroll
            for (int ni = 0; ni < 4; ni++) {
                mma_tf32(acc[mi][ni], lo.x, hi.x, lo.y, hi.y, bf[ni].x, bf[ni].y);
                mma_tf32(acc[mi][ni], lo.z, hi.z, lo.w, hi.w, bf[ni].z, bf[ni].w);
            }
        }
        __syncthreads();
    }

    // epilogue
#pragma unroll
    for (int mi = 0; mi < 4; mi++) {
        int r0 = rowBase + wm * 64 + mi * 16 + g;
#pragma unroll
        for (int ni = 0; ni < 4; ni++) {
            int cb = colBase + wn * 32 + ni * 8 + t4 * 2;
            float* a = acc[mi][ni];
#pragma unroll
            for (int half = 0; half < 2; half++) {
                int r = r0 + half * 8;
                if (r >= M) continue;
                size_t p = (size_t)r * N + cb;
                float v0 = a[half * 2], v1 = a[half * 2 + 1];
                if (gate != 0) {
                    v0 = sigmoidf_(v0 + bias[cb])     * X[p];
                    v1 = sigmoidf_(v1 + bias[cb + 1]) * X[p + 1];
                    if (gate == 2) { v0 += Y[p]; v1 += Y[p + 1]; }
                }
                if (Ch) {
                    *(half2*)(Ch + p) = __floats2half2_rn(v0, v1);
                } else {
                    C[p] = v0;
                    C[p + 1] = v1;
                }
            }
        }
    }
}

// ---------------- weight permute+round pre-pass --------------------------
__global__ void permute_round(const float* __restrict__ in, float* __restrict__ out, int n)
{
    int i = blockIdx.x * blockDim.x + threadIdx.x;
    if (i >= n) return;
    int p = i & 15;
    int k = (i & ~15) | (4 * (p & 3) + (p >> 2));
    out[i] = roundtf(in[k]);
}

// ---------------- 512x512 transpose (+ permute + round) ------------------
__global__ void transpose512(const float* __restrict__ in, float* __restrict__ out)
{
    __shared__ float t[32][33];
    int x = blockIdx.x * 32 + threadIdx.x;
    int y0 = blockIdx.y * 32;
#pragma unroll
    for (int i = threadIdx.y; i < 32; i += 8)
        t[i][threadIdx.x] = in[(size_t)(y0 + i) * 512 + x];
    __syncthreads();
    int ox = blockIdx.y * 32 + threadIdx.x;
    int q = (ox & ~15) | ((ox & 3) * 4 + ((ox >> 2) & 3));
    int oy0 = blockIdx.x * 32;
#pragma unroll
    for (int i = threadIdx.y; i < 32; i += 8)
        out[(size_t)(oy0 + i) * 512 + q] = roundtf(t[threadIdx.x][i]);
}

// ---------------- attention score reductions ----------------
// layer-1 scores from fp16 z1
__global__ void attn_scores8(const __half* __restrict__ z, const float* __restrict__ a,
                             float* __restrict__ ssrc, float* __restrict__ sdst, int n)
{
    int warp = (blockIdx.x * blockDim.x + threadIdx.x) >> 5;
    int lane = threadIdx.x & 31;
    if (warp >= n * HEADS) return;
    int node = warp >> 3, h = warp & 7;
    const __half* zr = z + (size_t)node * FUSEDD + h * HID;
    const float* ar = a + h * (2 * HID);
    float v0 = __half2float(zr[lane]), v1 = __half2float(zr[lane + 32]);
    float ss = v0 * ar[lane] + v1 * ar[lane + 32];
    float sd = v0 * ar[64 + lane] + v1 * ar[96 + lane];
#pragma unroll
    for (int d = 16; d; d >>= 1) {
        ss += __shfl_xor_sync(0xffffffffu, ss, d);
        sd += __shfl_xor_sync(0xffffffffu, sd, d);
    }
    if (lane == 0) { ssrc[warp] = ss; sdst[warp] = sd; }
}

__global__ void attn_scores1(const float* __restrict__ z, const float* __restrict__ a,
                             float* __restrict__ ssrc, float* __restrict__ sdst, int n)
{
    int warp = (blockIdx.x * blockDim.x + threadIdx.x) >> 5;
    int lane = threadIdx.x & 31;
    if (warp >= n) return;
    const float* zr = z + (size_t)warp * OUT_D;
    float ss = 0.f, sd = 0.f;
#pragma unroll
    for (int o = lane; o < OUT_D; o += 32) {
        float v = zr[o];
        ss += v * a[o];
        sd += v * a[OUT_D + o];
    }
#pragma unroll
    for (int d = 16; d; d >>= 1) {
        ss += __shfl_xor_sync(0xffffffffu, ss, d);
        sd += __shfl_xor_sync(0xffffffffu, sd, d);
    }
    if (lane == 0) { ssrc[warp] = ss; sdst[warp] = sd; }
}

// ---------------- per-layer init ----------------
__global__ void init_l1()
{
    int i = blockIdx.x * blockDim.x + threadIdx.x;
    if (i < N_DST0 * HEADS) g_den0[i] = 0.f;
    if (i < N_DST0) { g_cnt0[i] = 0; g_cur0[i] = 0; }
}
__global__ void init_l2()
{
    int i = blockIdx.x * blockDim.x + threadIdx.x;
    if (i < N_DST1) { g_den1[i] = 0.f; g_cnt1[i] = 0; g_cur1[i] = 0; }
}

// ---------------- edge softmax (max-free) + fused histogram ----------------
template <int H>
__global__ void edge_exp(const int* __restrict__ src, const int* __restrict__ dst,
                         const float* __restrict__ ssrc, const float* __restrict__ sdst,
                         float* __restrict__ w, float* __restrict__ den,
                         int* __restrict__ cnt, int E)
{
    int i = blockIdx.x * blockDim.x + threadIdx.x;
    if (i >= E * H) return;
    int e = i / H, h = i - e * H;
    int d = dst[e];
    float v = ssrc[src[e] * H + h] + sdst[d * H + h];
    v = v > 0.f ? v : 0.01f * v;
    float ex = __expf(v);
    w[i] = ex;
    atomicAdd(&den[d * H + h], ex);
    if (h == 0) atomicAdd(&cnt[d], 1);   // fused histogram
}

// ---------------- CSR build ----------------
__global__ void exscan_k(const int* __restrict__ cnt, int* __restrict__ off, int n)
{
    __shared__ int sm[1024];
    int tid = threadIdx.x;
    int chunk = (n + 1023) >> 10;
    int s = tid * chunk;
    int e = s + chunk < n ? s + chunk : n;
    int sum = 0;
    for (int i = s; i < e; i++) sum += cnt[i];
    sm[tid] = sum;
    __syncthreads();
    for (int d = 1; d < 1024; d <<= 1) {
        int t = (tid >= d) ? sm[tid - d] : 0;
        __syncthreads();
        sm[tid] += t;
        __syncthreads();
    }
    int run = sm[tid] - sum;
    for (int i = s; i < e; i++) { off[i] = run; run += cnt[i]; }
    if (tid == 1023) off[n] = sm[1023];
}

__global__ void scatter_k(const int* __restrict__ dst, const int* __restrict__ off,
                          int* __restrict__ cur, int* __restrict__ sorted, int E)
{
    int i = blockIdx.x * blockDim.x + threadIdx.x;
    if (i >= E) return;
    int d = dst[i];
    int p = atomicAdd(&cur[d], 1);
    sorted[off[d] + p] = i;
}

// ---------------- aggregation ----------------
// layer 1: block per dst node; 128 threads x 4 channels; z in fp16 (uint2
// gather = 1KB/row instead of 2KB); fp32 accumulate; fused ELU; fp32 out.
__global__ __launch_bounds__(128) void aggregate8_elu(
    const int* __restrict__ sorted, const int* __restrict__ off,
    const int* __restrict__ esrc, const float* __restrict__ w,
    const float* __restrict__ den, const __half* __restrict__ z,
    float* __restrict__ out)
{
    __shared__ int s_ed[128];
    __shared__ int s_src[128];
    int d = blockIdx.x;
    int t = threadIdx.x;
    int h = t >> 4;
    float4 acc = make_float4(0.f, 0.f, 0.f, 0.f);
    int s = off[d], e = off[d + 1];
    for (int base = s; base < e; base += 128) {
        int nch = min(128, e - base);
        __syncthreads();
        if (t < nch) {
            int ed = sorted[base + t];
            s_ed[t] = ed;
            s_src[t] = esrc[ed];
        }
        __syncthreads();
#pragma unroll 2
        for (int j = 0; j < nch; j++) {
            float alpha = w[(size_t)s_ed[j] * HEADS + h];
            uint2 u = *(const uint2*)(z + (size_t)s_src[j] * FUSEDD + t * 4);
            float2 f0 = __half22float2(*(const half2*)&u.x);
            float2 f1 = __half22float2(*(const half2*)&u.y);
            acc.x += alpha * f0.x;
            acc.y += alpha * f0.y;
            acc.z += alpha * f1.x;
            acc.w += alpha * f1.y;
        }
    }
    float inv = 1.f / den[d * HEADS + h];
    acc.x *= inv; acc.y *= inv; acc.z *= inv; acc.w *= inv;
    acc.x = acc.x > 0.f ? acc.x : (__expf(acc.x) - 1.f);
    acc.y = acc.y > 0.f ? acc.y : (__expf(acc.y) - 1.f);
    acc.z = acc.z > 0.f ? acc.z : (__expf(acc.z) - 1.f);
    acc.w = acc.w > 0.f ? acc.w : (__expf(acc.w) - 1.f);
    *(float4*)(out + (size_t)d * FUSEDD + t * 4) = acc;
}

__global__ __launch_bounds__(128) void aggregate1(
    const int* __restrict__ sorted, const int* __restrict__ off,
    const int* __restrict__ esrc, const float* __restrict__ w,
    const float* __restrict__ den, const float* __restrict__ z,
    float* __restrict__ out)
{
    __shared__ int s_src[128];
    __shared__ float s_w[128];
    int d = blockIdx.x;
    int c = threadIdx.x;
    float acc = 0.f;
    int s = off[d], e = off[d + 1];
    for (int base = s; base < e; base += 128) {
        int nch = min(128, e - base);
        __syncthreads();
        if (c < nch) {
            int ed = sorted[base + c];
            s_src[c] = esrc[ed];
            s_w[c] = w[ed];
        }
        __syncthreads();
#pragma unroll 4
        for (int j = 0; j < nch; j++)
            acc += s_w[j] * z[(size_t)s_src[j] * OUT_D + c];
    }
    out[(size_t)d * OUT_D + c] = acc / den[d];
}

// ---------------- host launcher ----------------
extern "C" void kernel_launch(void* const* d_in, const int* in_sizes, int n_in,
                              void* d_out, int out_size)
{
    (void)in_sizes; (void)n_in; (void)out_size;
    const float* img   = (const float*)d_in[0];
    const float* blk   = (const float*)d_in[1];
    const float* W_img = (const float*)d_in[2];
    const float* W_blk = (const float*)d_in[3];
    const float* Wv    = (const float*)d_in[4];
    const float* bv    = (const float*)d_in[5];
    const float* We    = (const float*)d_in[6];
    const float* be    = (const float*)d_in[7];
    const float* fc1   = (const float*)d_in[8];
    const float* attn1 = (const float*)d_in[9];
    const float* fc2   = (const float*)d_in[10];
    const float* attn2 = (const float*)d_in[11];
    const int* e0s = (const int*)d_in[12];
    const int* e0d = (const int*)d_in[13];
    const int* e1s = (const int*)d_in[14];
    const int* e1d = (const int*)d_in[15];
    float* out = (float*)d_out;

    float *fi, *ti, *c, *wT, *wBig;
    float *ssrc0, *sdst0, *den0, *w0;
    int *cnt0, *off0, *cur0, *sorted0;
    float *ssrc1, *sdst1, *den1, *w1;
    int *cnt1, *off1, *cur1, *sorted1;
    cudaGetSymbolAddress((void**)&fi, g_fi);
    cudaGetSymbolAddress((void**)&ti, g_ti);
    cudaGetSymbolAddress((void**)&c,  g_c);
    cudaGetSymbolAddress((void**)&wT, g_wT);
    cudaGetSymbolAddress((void**)&wBig, g_wBig);
    cudaGetSymbolAddress((void**)&ssrc0, g_ssrc0);
    cudaGetSymbolAddress((void**)&sdst0, g_sdst0);
    cudaGetSymbolAddress((void**)&den0, g_den0);
    cudaGetSymbolAddress((void**)&w0, g_w0);
    cudaGetSymbolAddress((void**)&cnt0, g_cnt0);
    cudaGetSymbolAddress((void**)&off0, g_off0);
    cudaGetSymbolAddress((void**)&cur0, g_cur0);
    cudaGetSymbolAddress((void**)&sorted0, g_sorted0);
    cudaGetSymbolAddress((void**)&ssrc1, g_ssrc1);
    cudaGetSymbolAddress((void**)&sdst1, g_sdst1);
    cudaGetSymbolAddress((void**)&den1, g_den1);
    cudaGetSymbolAddress((void**)&w1, g_w1);
    cudaGetSymbolAddress((void**)&cnt1, g_cnt1);
    cudaGetSymbolAddress((void**)&off1, g_off1);
    cudaGetSymbolAddress((void**)&cur1, g_cur1);
    cudaGetSymbolAddress((void**)&sorted1, g_sorted1);

    __half* tiH = (__half*)ti;   // fp16 z1 view (capacity: fp32 buffer)

    dim3 tb(256);
    dim3 gBig(FUSEDD / BN, (N_SRC0 + BM - 1) / BM);

    // 1: projection 1
    permute_round<<<(FUSEDD * IMG_D + 255) / 256, tb>>>(W_img, wBig, FUSEDD * IMG_D);
    gemm_tc<<<gBig, tb>>>(img, wBig, fi, nullptr, N_SRC0, FUSEDD, IMG_D, 0, nullptr, nullptr, nullptr);

    // 2: projection 2
    permute_round<<<(FUSEDD * BLK_D + 255) / 256, tb>>>(W_blk, wBig, FUSEDD * BLK_D);
    gemm_tc<<<gBig, tb>>>(blk, wBig, ti, nullptr, N_SRC0, FUSEDD, BLK_D, 0, nullptr, nullptr, nullptr);

    // 3: visual gate fused: c = sigmoid(fi@Wv + bv) * fi
    transpose512<<<dim3(16, 16), dim3(32, 8)>>>(Wv, wT);
    gemm_tc<<<gBig, tb>>>(fi, wT, c, nullptr, N_SRC0, FUSEDD, FUSEDD, 1, bv, fi, nullptr);

    // 4: edge gate fused: c = sigmoid(ti@We + be) * ti + c  (c = fused)
    transpose512<<<dim3(16, 16), dim3(32, 8)>>>(We, wT);
    gemm_tc<<<gBig, tb>>>(ti, wT, c, nullptr, N_SRC0, FUSEDD, FUSEDD, 2, be, ti, c);

    // 5: z1 = fused @ fc1^T -> fp16 (tiH)
    permute_round<<<(FUSEDD * FUSEDD + 255) / 256, tb>>>(fc1, wBig, FUSEDD * FUSEDD);
    gemm_tc<<<gBig, tb>>>(c, wBig, nullptr, tiH, N_SRC0, FUSEDD, FUSEDD, 0, nullptr, nullptr, nullptr);

    // 6: attention scores layer 1 (fp16 z)
    attn_scores8<<<(N_SRC0 * HEADS * 32 + 255) / 256, tb>>>(tiH, attn1, ssrc0, sdst0, N_SRC0);

    // 7-11: edge softmax (+fused hist) + CSR + aggregate (layer 1) -> fi
    init_l1<<<(N_DST0 * HEADS + 255) / 256, tb>>>();
    edge_exp<HEADS><<<(E0 * HEADS + 255) / 256, tb>>>(e0s, e0d, ssrc0, sdst0, w0, den0, cnt0, E0);
    exscan_k<<<1, 1024>>>(cnt0, off0, N_DST0);
    scatter_k<<<(E0 + 255) / 256, tb>>>(e0d, off0, cur0, sorted0, E0);
    aggregate8_elu<<<N_DST0, 128>>>(sorted0, off0, e0s, w0, den0, tiH, fi);

    // 12: z2 = h @ fc2^T -> c
    permute_round<<<(OUT_D * FUSEDD + 255) / 256, tb>>>(fc2, wBig, OUT_D * FUSEDD);
    gemm_tc<<<dim3(OUT_D / BN, (N_SRC1 + BM - 1) / BM), tb>>>(fi, wBig, c, nullptr, N_SRC1, OUT_D, FUSEDD, 0, nullptr, nullptr, nullptr);

    // 13-18: layer 2 edge softmax + aggregate -> d_out
    attn_scores1<<<(N_SRC1 * 32 + 255) / 256, tb>>>(c, attn2, ssrc1, sdst1, N_SRC1);
    init_l2<<<(N_DST1 + 255) / 256, tb>>>();
    edge_exp<1><<<(E1 + 255) / 256, tb>>>(e1s, e1d, ssrc1, sdst1, w1, den1, cnt1, E1);
    exscan_k<<<1, 1024>>>(cnt1, off1, N_DST1);
    scatter_k<<<(E1 + 255) / 256, tb>>>(e1d, off1, cur1, sorted1, E1);
    aggregate1<<<N_DST1, 128>>>(sorted1, off1, e1s, w1, den1, c, out);
}

// round 16
// speedup vs baseline: 2.2004x; 1.5251x over previous
#include <cuda_runtime.h>
#include <cuda_fp16.h>
#include <cstdint>

// ---------------- problem constants (fixed by the dataset) ----------------
#define N_SRC0 60000
#define N_DST0 30000
#define E0     480000
#define N_SRC1 30000
#define N_DST1 8000
#define E1     128000
#define IMG_D  1024
#define BLK_D  768
#define FUSEDD 512
#define HEADS  8
#define HID    64
#define OUT_D  128

// ---------------- device scratch (static: no runtime allocation) ----------
// fp16 views carved out of fp32-sized buffers (capacity ample)
__device__ float g_fi[(size_t)N_SRC0 * FUSEDD];   // __half fi -> h1
__device__ float g_ti[(size_t)N_SRC0 * FUSEDD];   // __half ti -> z1
__device__ float g_c [(size_t)N_SRC0 * FUSEDD];   // __half fused -> z2
__device__ float g_wT[FUSEDD * FUSEDD];           // __half permuted WvT/WeT
__device__ float g_wBig[FUSEDD * IMG_D];          // __half permuted weights

__device__ float g_ssrc0[N_SRC0 * HEADS], g_sdst0[N_SRC0 * HEADS];
__device__ float g_den0[N_DST0 * HEADS];
__device__ float g_w0[(size_t)E0 * HEADS];
__device__ int   g_cnt0[N_DST0], g_off0[N_DST0 + 1], g_cur0[N_DST0], g_sorted0[E0];

__device__ float g_ssrc1[N_SRC1], g_sdst1[N_SRC1];
__device__ float g_den1[N_DST1];
__device__ float g_w1[E1];
__device__ int   g_cnt1[N_DST1], g_off1[N_DST1 + 1], g_cur1[N_DST1], g_sorted1[E1];

// ---------------- helpers ----------------
__device__ __forceinline__ float sigmoidf_(float x) {
    return 1.f / (1.f + __expf(-x));
}

// bit-cast half2 -> uint32 (register rename; __half2_as_uint doesn't exist)
__device__ __forceinline__ uint32_t h2u(half2 v) {
    union { half2 h; uint32_t u; } cvt;
    cvt.h = v;
    return cvt.u;
}

__device__ __forceinline__ void mma_f16(float* d, uint32_t a0, uint32_t a1,
                                        uint32_t a2, uint32_t a3,
                                        uint32_t b0, uint32_t b1) {
    asm volatile(
        "mma.sync.aligned.m16n8k16.row.col.f32.f16.f16.f32 "
        "{%0,%1,%2,%3}, {%4,%5,%6,%7}, {%8,%9}, {%0,%1,%2,%3};\n"
        : "+f"(d[0]), "+f"(d[1]), "+f"(d[2]), "+f"(d[3])
        : "r"(a0), "r"(a1), "r"(a2), "r"(a3), "r"(b0), "r"(b1));
}

// ---------------- fp16 tensor-core GEMM ---------------------------------
// C[M,N] = A[M,K] @ B[N,K]^T. fp32 accumulate, fp16 operands/outputs.
// 128x128 tile, BK=32 halves (64B rows), 8 warps 2(M)x4(N), warp 64x32.
// Smem A: 128 rows x 16 words (8KB). Word-level k-permute within 32-k
// groups: logical word position q holds orig k-pair w(q)=4*(q&3)+(q>>2)
// (involution); quarter XOR swizzle (j^((r>>1)&3)) -> STS.32 and fragment
// LDS.128 both bank-conflict-free (same algebra as validated tf32 layout).
// Fragment LDS.128 at logical quarter t4 yields orig words {t4,t4+4,t4+8,
// t4+12} = (step0 a0/a2, step1 a0/a2). B pre-permuted fp16 in GLOBAL:
// one LDG.128 per n-tile covers K=32 (.x/.y = step0 b0/b1, .z/.w = step1).
// AF16: A already fp16 (natural order); else fp32, converted in staging.
// gate: 0 plain, 1 C=sig(acc+b)*X, 2 C=sig(acc+b)*X+Y. C fp16 (half2).
#define BM 128
#define BN 128
#define BKH 32

template <bool AF16>
__global__ __launch_bounds__(256, 2) void gemm_hc(
    const void* __restrict__ Av, const __half* __restrict__ Bp,
    __half* __restrict__ C, int M, int N, int K, int gate,
    const float* __restrict__ bias, const __half* __restrict__ X,
    const __half* __restrict__ Y)
{
    __shared__ uint32_t As[BM * 16];

    const int tid  = threadIdx.x;
    const int warp = tid >> 5;
    const int lane = tid & 31;
    const int g    = lane >> 2;
    const int t4   = lane & 3;
    const int wm   = warp & 1;
    const int wn   = warp >> 1;
    const int rowBase = blockIdx.y * BM;
    const int colBase = blockIdx.x * BN;
    const int chA = ((t4 ^ ((g >> 1) & 3)) << 2);  // fragment quarter offset

    float acc[4][4][4];
#pragma unroll
    for (int i = 0; i < 4; i++)
#pragma unroll
        for (int j = 0; j < 4; j++)
#pragma unroll
            for (int r = 0; r < 4; r++) acc[i][j][r] = 0.f;

    // B fragment pointers: permuted fp16 weights, word pos 4*t4 = half 8*t4
    const __half* bRow[4];
#pragma unroll
    for (int ni = 0; ni < 4; ni++)
        bRow[ni] = Bp + (size_t)(colBase + wn * 32 + ni * 8 + g) * K + 8 * t4;

    // staging: f = tid + l*256, row r = f>>2, quarter c = f&3
    float4 sf[2][2];   // fp32 path
    uint4  sh[2];      // fp16 path

    auto g2r = [&](int k0) {
#pragma unroll
        for (int l = 0; l < 2; l++) {
            int f = tid + l * 256;
            int r = f >> 2, c = f & 3;
            int gr = rowBase + r;
            gr = gr < M ? gr : M - 1;
            if (AF16) {
                sh[l] = *(const uint4*)((const __half*)Av + (size_t)gr * K + k0 + 8 * c);
            } else {
                const float* Af = (const float*)Av + (size_t)gr * K + k0 + 8 * c;
                sf[l][0] = *(const float4*)Af;
                sf[l][1] = *(const float4*)(Af + 4);
            }
        }
    };
    auto r2s = [&]() {
#pragma unroll
        for (int l = 0; l < 2; l++) {
            int f = tid + l * 256;
            int r = f >> 2, c = f & 3;
            int sw = (r >> 1) & 3;
            uint32_t w[4];
            if (AF16) {
                w[0] = sh[l].x; w[1] = sh[l].y; w[2] = sh[l].z; w[3] = sh[l].w;
            } else {
                w[0] = h2u(__floats2half2_rn(sf[l][0].x, sf[l][0].y));
                w[1] = h2u(__floats2half2_rn(sf[l][0].z, sf[l][0].w));
                w[2] = h2u(__floats2half2_rn(sf[l][1].x, sf[l][1].y));
                w[3] = h2u(__floats2half2_rn(sf[l][1].z, sf[l][1].w));
            }
            uint32_t* pa = &As[r * 16 + c];
#pragma unroll
            for (int j = 0; j < 4; j++)
                pa[((j ^ sw) << 2)] = w[j];
        }
    };

    g2r(0);

    for (int k0 = 0; k0 < K; k0 += BKH) {
        r2s();
        __syncthreads();
        if (k0 + BKH < K) g2r(k0 + BKH);

        uint4 bf[4];
#pragma unroll
        for (int ni = 0; ni < 4; ni++)
            bf[ni] = *(const uint4*)(bRow[ni] + k0);

#pragma unroll
        for (int mi = 0; mi < 4; mi++) {
            int m0 = wm * 64 + mi * 16;
            uint4 lo = *(const uint4*)&As[(m0 + g) * 16 + chA];
            uint4 hi = *(const uint4*)&As[(m0 + 8 + g) * 16 + chA];
#pragma unroll
            for (int ni = 0; ni < 4; ni++) {
                mma_f16(acc[mi][ni], lo.x, hi.x, lo.y, hi.y, bf[ni].x, bf[ni].y);
                mma_f16(acc[mi][ni], lo.z, hi.z, lo.w, hi.w, bf[ni].z, bf[ni].w);
            }
        }
        __syncthreads();
    }

    // epilogue: fp16 half2 stores
#pragma unroll
    for (int mi = 0; mi < 4; mi++) {
        int r0 = rowBase + wm * 64 + mi * 16 + g;
#pragma unroll
        for (int ni = 0; ni < 4; ni++) {
            int cb = colBase + wn * 32 + ni * 8 + t4 * 2;
            float* a = acc[mi][ni];
#pragma unroll
            for (int half = 0; half < 2; half++) {
                int r = r0 + half * 8;
                if (r >= M) continue;
                size_t p = (size_t)r * N + cb;
                float v0 = a[half * 2], v1 = a[half * 2 + 1];
                if (gate != 0) {
                    float2 x = __half22float2(*(const half2*)(X + p));
                    v0 = sigmoidf_(v0 + bias[cb])     * x.x;
                    v1 = sigmoidf_(v1 + bias[cb + 1]) * x.y;
                    if (gate == 2) {
                        float2 y = __half22float2(*(const half2*)(Y + p));
                        v0 += y.x; v1 += y.y;
                    }
                }
                *(half2*)(C + p) = __floats2half2_rn(v0, v1);
            }
        }
    }
}

// ---------------- weight permute+convert pre-pass ------------------------
// fp32 in -> fp16 out, word-level permute within 32-k groups:
// out word position q holds in k-pair starting at k = 2*(4*(q&3)+(q>>2)).
__global__ void permute_h(const float* __restrict__ in, __half2* __restrict__ out, int nWords)
{
    int i = blockIdx.x * blockDim.x + threadIdx.x;
    if (i >= nWords) return;
    int q = i & 15;
    int w = 4 * (q & 3) + (q >> 2);
    int k = ((i & ~15) << 1) + 2 * w;
    out[i] = __floats2half2_rn(in[k], in[k + 1]);
}

// ---------------- 512x512 transpose (+ permute + fp16) -------------------
__global__ void transpose512h(const float* __restrict__ in, __half* __restrict__ out)
{
    __shared__ float t[32][33];
    int x = blockIdx.x * 32 + threadIdx.x;
    int y0 = blockIdx.y * 32;
#pragma unroll
    for (int i = threadIdx.y; i < 32; i += 8)
        t[i][threadIdx.x] = in[(size_t)(y0 + i) * 512 + x];
    __syncthreads();
    int ox = blockIdx.y * 32 + threadIdx.x;            // k index of output
    int grp = ox >> 5, o = ox & 31, pr = o >> 1;
    int q = 4 * (pr & 3) + (pr >> 2);
    int pos = (grp << 5) + 2 * q + (o & 1);
    int oy0 = blockIdx.x * 32;
#pragma unroll
    for (int i = threadIdx.y; i < 32; i += 8)
        out[(size_t)(oy0 + i) * 512 + pos] = __float2half_rn(t[threadIdx.x][i]);
}

// ---------------- attention score reductions ----------------
__global__ void attn_scores8(const __half* __restrict__ z, const float* __restrict__ a,
                             float* __restrict__ ssrc, float* __restrict__ sdst, int n)
{
    int warp = (blockIdx.x * blockDim.x + threadIdx.x) >> 5;
    int lane = threadIdx.x & 31;
    if (warp >= n * HEADS) return;
    int node = warp >> 3, h = warp & 7;
    const __half* zr = z + (size_t)node * FUSEDD + h * HID;
    const float* ar = a + h * (2 * HID);
    float v0 = __half2float(zr[lane]), v1 = __half2float(zr[lane + 32]);
    float ss = v0 * ar[lane] + v1 * ar[lane + 32];
    float sd = v0 * ar[64 + lane] + v1 * ar[96 + lane];
#pragma unroll
    for (int d = 16; d; d >>= 1) {
        ss += __shfl_xor_sync(0xffffffffu, ss, d);
        sd += __shfl_xor_sync(0xffffffffu, sd, d);
    }
    if (lane == 0) { ssrc[warp] = ss; sdst[warp] = sd; }
}

__global__ void attn_scores1(const __half* __restrict__ z, const float* __restrict__ a,
                             float* __restrict__ ssrc, float* __restrict__ sdst, int n)
{
    int warp = (blockIdx.x * blockDim.x + threadIdx.x) >> 5;
    int lane = threadIdx.x & 31;
    if (warp >= n) return;
    const __half* zr = z + (size_t)warp * OUT_D;
    float ss = 0.f, sd = 0.f;
#pragma unroll
    for (int o = lane; o < OUT_D; o += 32) {
        float v = __half2float(zr[o]);
        ss += v * a[o];
        sd += v * a[OUT_D + o];
    }
#pragma unroll
    for (int d = 16; d; d >>= 1) {
        ss += __shfl_xor_sync(0xffffffffu, ss, d);
        sd += __shfl_xor_sync(0xffffffffu, sd, d);
    }
    if (lane == 0) { ssrc[warp] = ss; sdst[warp] = sd; }
}

// ---------------- per-layer init ----------------
__global__ void init_l1()
{
    int i = blockIdx.x * blockDim.x + threadIdx.x;
    if (i < N_DST0 * HEADS) g_den0[i] = 0.f;
    if (i < N_DST0) { g_cnt0[i] = 0; g_cur0[i] = 0; }
}
__global__ void init_l2()
{
    int i = blockIdx.x * blockDim.x + threadIdx.x;
    if (i < N_DST1) { g_den1[i] = 0.f; g_cnt1[i] = 0; g_cur1[i] = 0; }
}

// ---------------- edge softmax (max-free) + fused histogram --------------
template <int H>
__global__ void edge_exp(const int* __restrict__ src, const int* __restrict__ dst,
                         const float* __restrict__ ssrc, const float* __restrict__ sdst,
                         float* __restrict__ w, float* __restrict__ den,
                         int* __restrict__ cnt, int E)
{
    int i = blockIdx.x * blockDim.x + threadIdx.x;
    if (i >= E * H) return;
    int e = i / H, h = i - e * H;
    int d = dst[e];
    float v = ssrc[src[e] * H + h] + sdst[d * H + h];
    v = v > 0.f ? v : 0.01f * v;
    float ex = __expf(v);
    w[i] = ex;
    atomicAdd(&den[d * H + h], ex);
    if (h == 0) atomicAdd(&cnt[d], 1);
}

// ---------------- CSR build ----------------
__global__ void exscan_k(const int* __restrict__ cnt, int* __restrict__ off, int n)
{
    __shared__ int sm[1024];
    int tid = threadIdx.x;
    int chunk = (n + 1023) >> 10;
    int s = tid * chunk;
    int e = s + chunk < n ? s + chunk : n;
    int sum = 0;
    for (int i = s; i < e; i++) sum += cnt[i];
    sm[tid] = sum;
    __syncthreads();
    for (int d = 1; d < 1024; d <<= 1) {
        int t = (tid >= d) ? sm[tid - d] : 0;
        __syncthreads();
        sm[tid] += t;
        __syncthreads();
    }
    int run = sm[tid] - sum;
    for (int i = s; i < e; i++) { off[i] = run; run += cnt[i]; }
    if (tid == 1023) off[n] = sm[1023];
}

__global__ void scatter_k(const int* __restrict__ dst, const int* __restrict__ off,
                          int* __restrict__ cur, int* __restrict__ sorted, int E)
{
    int i = blockIdx.x * blockDim.x + threadIdx.x;
    if (i >= E) return;
    int d = dst[i];
    int p = atomicAdd(&cur[d], 1);
    sorted[off[d] + p] = i;
}

// ---------------- aggregation ----------------
// layer 1: block per dst node; 128 threads x 4 channels; z fp16 (uint2
// gather); fp32 accumulate; fused ELU; fp16 output (feeds z2 GEMM A).
__global__ __launch_bounds__(128) void aggregate8_elu(
    const int* __restrict__ sorted, const int* __restrict__ off,
    const int* __restrict__ esrc, const float* __restrict__ w,
    const float* __restrict__ den, const __half* __restrict__ z,
    __half* __restrict__ out)
{
    __shared__ int s_ed[128];
    __shared__ int s_src[128];
    int d = blockIdx.x;
    int t = threadIdx.x;
    int h = t >> 4;
    float4 acc = make_float4(0.f, 0.f, 0.f, 0.f);
    int s = off[d], e = off[d + 1];
    for (int base = s; base < e; base += 128) {
        int nch = min(128, e - base);
        __syncthreads();
        if (t < nch) {
            int ed = sorted[base + t];
            s_ed[t] = ed;
            s_src[t] = esrc[ed];
        }
        __syncthreads();
#pragma unroll 2
        for (int j = 0; j < nch; j++) {
            float alpha = w[(size_t)s_ed[j] * HEADS + h];
            uint2 u = *(const uint2*)(z + (size_t)s_src[j] * FUSEDD + t * 4);
            float2 f0 = __half22float2(*(const half2*)&u.x);
            float2 f1 = __half22float2(*(const half2*)&u.y);
            acc.x += alpha * f0.x;
            acc.y += alpha * f0.y;
            acc.z += alpha * f1.x;
            acc.w += alpha * f1.y;
        }
    }
    float inv = 1.f / den[d * HEADS + h];
    acc.x *= inv; acc.y *= inv; acc.z *= inv; acc.w *= inv;
    acc.x = acc.x > 0.f ? acc.x : (__expf(acc.x) - 1.f);
    acc.y = acc.y > 0.f ? acc.y : (__expf(acc.y) - 1.f);
    acc.z = acc.z > 0.f ? acc.z : (__expf(acc.z) - 1.f);
    acc.w = acc.w > 0.f ? acc.w : (__expf(acc.w) - 1.f);
    uint2 st;
    st.x = h2u(__floats2half2_rn(acc.x, acc.y));
    st.y = h2u(__floats2half2_rn(acc.z, acc.w));
    *(uint2*)(out + (size_t)d * FUSEDD + t * 4) = st;
}

__global__ __launch_bounds__(128) void aggregate1(
    const int* __restrict__ sorted, const int* __restrict__ off,
    const int* __restrict__ esrc, const float* __restrict__ w,
    const float* __restrict__ den, const __half* __restrict__ z,
    float* __restrict__ out)
{
    __shared__ int s_src[128];
    __shared__ float s_w[128];
    int d = blockIdx.x;
    int c = threadIdx.x;
    float acc = 0.f;
    int s = off[d], e = off[d + 1];
    for (int base = s; base < e; base += 128) {
        int nch = min(128, e - base);
        __syncthreads();
        if (c < nch) {
            int ed = sorted[base + c];
            s_src[c] = esrc[ed];
            s_w[c] = w[ed];
        }
        __syncthreads();
#pragma unroll 4
        for (int j = 0; j < nch; j++)
            acc += s_w[j] * __half2float(z[(size_t)s_src[j] * OUT_D + c]);
    }
    out[(size_t)d * OUT_D + c] = acc / den[d];
}

// ---------------- host launcher ----------------
extern "C" void kernel_launch(void* const* d_in, const int* in_sizes, int n_in,
                              void* d_out, int out_size)
{
    (void)in_sizes; (void)n_in; (void)out_size;
    const float* img   = (const float*)d_in[0];
    const float* blk   = (const float*)d_in[1];
    const float* W_img = (const float*)d_in[2];
    const float* W_blk = (const float*)d_in[3];
    const float* Wv    = (const float*)d_in[4];
    const float* bv    = (const float*)d_in[5];
    const float* We    = (const float*)d_in[6];
    const float* be    = (const float*)d_in[7];
    const float* fc1   = (const float*)d_in[8];
    const float* attn1 = (const float*)d_in[9];
    const float* fc2   = (const float*)d_in[10];
    const float* attn2 = (const float*)d_in[11];
    const int* e0s = (const int*)d_in[12];
    const int* e0d = (const int*)d_in[13];
    const int* e1s = (const int*)d_in[14];
    const int* e1d = (const int*)d_in[15];
    float* out = (float*)d_out;

    float *fi, *ti, *c, *wT, *wBig;
    float *ssrc0, *sdst0, *den0, *w0;
    int *cnt0, *off0, *cur0, *sorted0;
    float *ssrc1, *sdst1, *den1, *w1;
    int *cnt1, *off1, *cur1, *sorted1;
    cudaGetSymbolAddress((void**)&fi, g_fi);
    cudaGetSymbolAddress((void**)&ti, g_ti);
    cudaGetSymbolAddress((void**)&c,  g_c);
    cudaGetSymbolAddress((void**)&wT, g_wT);
    cudaGetSymbolAddress((void**)&wBig, g_wBig);
    cudaGetSymbolAddress((void**)&ssrc0, g_ssrc0);
    cudaGetSymbolAddress((void**)&sdst0, g_sdst0);
    cudaGetSymbolAddress((void**)&den0, g_den0);
    cudaGetSymbolAddress((void**)&w0, g_w0);
    cudaGetSymbolAddress((void**)&cnt0, g_cnt0);
    cudaGetSymbolAddress((void**)&off0, g_off0);
    cudaGetSymbolAddress((void**)&cur0, g_cur0);
    cudaGetSymbolAddress((void**)&sorted0, g_sorted0);
    cudaGetSymbolAddress((void**)&ssrc1, g_ssrc1);
    cudaGetSymbolAddress((void**)&sdst1, g_sdst1);
    cudaGetSymbolAddress((void**)&den1, g_den1);
    cudaGetSymbolAddress((void**)&w1, g_w1);
    cudaGetSymbolAddress((void**)&cnt1, g_cnt1);
    cudaGetSymbolAddress((void**)&off1, g_off1);
    cudaGetSymbolAddress((void**)&cur1, g_cur1);
    cudaGetSymbolAddress((void**)&sorted1, g_sorted1);

    __half* fiH = (__half*)fi;
    __half* tiH = (__half*)ti;
    __half* cH  = (__half*)c;
    __half* wTH = (__half*)wT;
    __half* wBigH = (__half*)wBig;

    dim3 tb(256);
    dim3 gBig(FUSEDD / BN, (N_SRC0 + BM - 1) / BM);

    // 1: projection 1 (A = img fp32, converted in staging)
    permute_h<<<(FUSEDD * IMG_D / 2 + 255) / 256, tb>>>(W_img, (__half2*)wBigH, FUSEDD * IMG_D / 2);
    gemm_hc<false><<<gBig, tb>>>(img, wBigH, fiH, N_SRC0, FUSEDD, IMG_D, 0, nullptr, nullptr, nullptr);

    // 2: projection 2
    permute_h<<<(FUSEDD * BLK_D / 2 + 255) / 256, tb>>>(W_blk, (__half2*)wBigH, FUSEDD * BLK_D / 2);
    gemm_hc<false><<<gBig, tb>>>(blk, wBigH, tiH, N_SRC0, FUSEDD, BLK_D, 0, nullptr, nullptr, nullptr);

    // 3: visual gate fused: c = sigmoid(fi@Wv + bv) * fi
    transpose512h<<<dim3(16, 16), dim3(32, 8)>>>(Wv, wTH);
    gemm_hc<true><<<gBig, tb>>>(fiH, wTH, cH, N_SRC0, FUSEDD, FUSEDD, 1, bv, fiH, nullptr);

    // 4: edge gate fused: c = sigmoid(ti@We + be) * ti + c  (c = fused)
    transpose512h<<<dim3(16, 16), dim3(32, 8)>>>(We, wTH);
    gemm_hc<true><<<gBig, tb>>>(tiH, wTH, cH, N_SRC0, FUSEDD, FUSEDD, 2, be, tiH, cH);

    // 5: z1 = fused @ fc1^T -> tiH
    permute_h<<<(FUSEDD * FUSEDD / 2 + 255) / 256, tb>>>(fc1, (__half2*)wBigH, FUSEDD * FUSEDD / 2);
    gemm_hc<true><<<gBig, tb>>>(cH, wBigH, tiH, N_SRC0, FUSEDD, FUSEDD, 0, nullptr, nullptr, nullptr);

    // 6: attention scores layer 1
    attn_scores8<<<(N_SRC0 * HEADS * 32 + 255) / 256, tb>>>(tiH, attn1, ssrc0, sdst0, N_SRC0);

    // 7-11: edge softmax (+fused hist) + CSR + aggregate -> fiH (h1)
    init_l1<<<(N_DST0 * HEADS + 255) / 256, tb>>>();
    edge_exp<HEADS><<<(E0 * HEADS + 255) / 256, tb>>>(e0s, e0d, ssrc0, sdst0, w0, den0, cnt0, E0);
    exscan_k<<<1, 1024>>>(cnt0, off0, N_DST0);
    scatter_k<<<(E0 + 255) / 256, tb>>>(e0d, off0, cur0, sorted0, E0);
    aggregate8_elu<<<N_DST0, 128>>>(sorted0, off0, e0s, w0, den0, tiH, fiH);

    // 12: z2 = h1 @ fc2^T -> cH
    permute_h<<<(OUT_D * FUSEDD / 2 + 255) / 256, tb>>>(fc2, (__half2*)wBigH, OUT_D * FUSEDD / 2);
    gemm_hc<true><<<dim3(OUT_D / BN, (N_SRC1 + BM - 1) / BM), tb>>>(fiH, wBigH, cH, N_SRC1, OUT_D, FUSEDD, 0, nullptr, nullptr, nullptr);

    // 13-17: layer 2 edge softmax + aggregate -> d_out (fp32)
    attn_scores1<<<(N_SRC1 * 32 + 255) / 256, tb>>>(cH, attn2, ssrc1, sdst1, N_SRC1);
    init_l2<<<(N_DST1 + 255) / 256, tb>>>();
    edge_exp<1><<<(E1 + 255) / 256, tb>>>(e1s, e1d, ssrc1, sdst1, w1, den1, cnt1, E1);
    exscan_k<<<1, 1024>>>(cnt1, off1, N_DST1);
    scatter_k<<<(E1 + 255) / 256, tb>>>(e1d, off1, cur1, sorted1, E1);
    aggregate1<<<N_DST1, 128>>>(sorted1, off1, e1s, w1, den1, cH, out);
}

// round 17
// speedup vs baseline: 2.2267x; 1.0120x over previous
#include <cuda_runtime.h>
#include <cuda_fp16.h>
#include <cstdint>

// ---------------- problem constants (fixed by the dataset) ----------------
#define N_SRC0 60000
#define N_DST0 30000
#define E0     480000
#define N_SRC1 30000
#define N_DST1 8000
#define E1     128000
#define IMG_D  1024
#define BLK_D  768
#define FUSEDD 512
#define HEADS  8
#define HID    64
#define OUT_D  128

// ---------------- device scratch (static: no runtime allocation) ----------
// fp16 views carved out of fp32-sized buffers (capacity ample)
__device__ float g_fi[(size_t)N_SRC0 * FUSEDD];   // __half fi -> h1
__device__ float g_ti[(size_t)N_SRC0 * FUSEDD];   // __half ti -> z1
__device__ float g_c [(size_t)N_SRC0 * FUSEDD];   // __half fused -> z2
__device__ float g_wT[FUSEDD * FUSEDD];           // __half permuted WvT/WeT
__device__ float g_wBig[FUSEDD * IMG_D];          // __half permuted weights

__device__ float g_ssrc0[N_SRC0 * HEADS], g_sdst0[N_SRC0 * HEADS];
__device__ float g_den0[N_DST0 * HEADS];
__device__ float g_w0[(size_t)E0 * HEADS];        // __half view used
__device__ int   g_cnt0[N_DST0], g_off0[N_DST0 + 1], g_cur0[N_DST0], g_sorted0[E0];

__device__ float g_ssrc1[N_SRC1], g_sdst1[N_SRC1];
__device__ float g_den1[N_DST1];
__device__ float g_w1[E1];                        // __half view used
__device__ int   g_cnt1[N_DST1], g_off1[N_DST1 + 1], g_cur1[N_DST1], g_sorted1[E1];

// ---------------- helpers ----------------
__device__ __forceinline__ float sigmoidf_(float x) {
    return 1.f / (1.f + __expf(-x));
}

__device__ __forceinline__ uint32_t h2u(half2 v) {
    union { half2 h; uint32_t u; } cvt;
    cvt.h = v;
    return cvt.u;
}

__device__ __forceinline__ void mma_f16(float* d, uint32_t a0, uint32_t a1,
                                        uint32_t a2, uint32_t a3,
                                        uint32_t b0, uint32_t b1) {
    asm volatile(
        "mma.sync.aligned.m16n8k16.row.col.f32.f16.f16.f32 "
        "{%0,%1,%2,%3}, {%4,%5,%6,%7}, {%8,%9}, {%0,%1,%2,%3};\n"
        : "+f"(d[0]), "+f"(d[1]), "+f"(d[2]), "+f"(d[3])
        : "r"(a0), "r"(a1), "r"(a2), "r"(a3), "r"(b0), "r"(b1));
}

// ---------------- fp16 tensor-core GEMM (R16-proven, unchanged) ----------
#define BM 128
#define BN 128
#define BKH 32

template <bool AF16>
__global__ __launch_bounds__(256, 2) void gemm_hc(
    const void* __restrict__ Av, const __half* __restrict__ Bp,
    __half* __restrict__ C, int M, int N, int K, int gate,
    const float* __restrict__ bias, const __half* __restrict__ X,
    const __half* __restrict__ Y)
{
    __shared__ uint32_t As[BM * 16];

    const int tid  = threadIdx.x;
    const int warp = tid >> 5;
    const int lane = tid & 31;
    const int g    = lane >> 2;
    const int t4   = lane & 3;
    const int wm   = warp & 1;
    const int wn   = warp >> 1;
    const int rowBase = blockIdx.y * BM;
    const int colBase = blockIdx.x * BN;
    const int chA = ((t4 ^ ((g >> 1) & 3)) << 2);

    float acc[4][4][4];
#pragma unroll
    for (int i = 0; i < 4; i++)
#pragma unroll
        for (int j = 0; j < 4; j++)
#pragma unroll
            for (int r = 0; r < 4; r++) acc[i][j][r] = 0.f;

    const __half* bRow[4];
#pragma unroll
    for (int ni = 0; ni < 4; ni++)
        bRow[ni] = Bp + (size_t)(colBase + wn * 32 + ni * 8 + g) * K + 8 * t4;

    float4 sf[2][2];
    uint4  sh[2];

    auto g2r = [&](int k0) {
#pragma unroll
        for (int l = 0; l < 2; l++) {
            int f = tid + l * 256;
            int r = f >> 2, c = f & 3;
            int gr = rowBase + r;
            gr = gr < M ? gr : M - 1;
            if (AF16) {
                sh[l] = *(const uint4*)((const __half*)Av + (size_t)gr * K + k0 + 8 * c);
            } else {
                const float* Af = (const float*)Av + (size_t)gr * K + k0 + 8 * c;
                sf[l][0] = *(const float4*)Af;
                sf[l][1] = *(const float4*)(Af + 4);
            }
        }
    };
    auto r2s = [&]() {
#pragma unroll
        for (int l = 0; l < 2; l++) {
            int f = tid + l * 256;
            int r = f >> 2, c = f & 3;
            int sw = (r >> 1) & 3;
            uint32_t w[4];
            if (AF16) {
                w[0] = sh[l].x; w[1] = sh[l].y; w[2] = sh[l].z; w[3] = sh[l].w;
            } else {
                w[0] = h2u(__floats2half2_rn(sf[l][0].x, sf[l][0].y));
                w[1] = h2u(__floats2half2_rn(sf[l][0].z, sf[l][0].w));
                w[2] = h2u(__floats2half2_rn(sf[l][1].x, sf[l][1].y));
                w[3] = h2u(__floats2half2_rn(sf[l][1].z, sf[l][1].w));
            }
            uint32_t* pa = &As[r * 16 + c];
#pragma unroll
            for (int j = 0; j < 4; j++)
                pa[((j ^ sw) << 2)] = w[j];
        }
    };

    g2r(0);

    for (int k0 = 0; k0 < K; k0 += BKH) {
        r2s();
        __syncthreads();
        if (k0 + BKH < K) g2r(k0 + BKH);

        uint4 bf[4];
#pragma unroll
        for (int ni = 0; ni < 4; ni++)
            bf[ni] = *(const uint4*)(bRow[ni] + k0);

#pragma unroll
        for (int mi = 0; mi < 4; mi++) {
            int m0 = wm * 64 + mi * 16;
            uint4 lo = *(const uint4*)&As[(m0 + g) * 16 + chA];
            uint4 hi = *(const uint4*)&As[(m0 + 8 + g) * 16 + chA];
#pragma unroll
            for (int ni = 0; ni < 4; ni++) {
                mma_f16(acc[mi][ni], lo.x, hi.x, lo.y, hi.y, bf[ni].x, bf[ni].y);
                mma_f16(acc[mi][ni], lo.z, hi.z, lo.w, hi.w, bf[ni].z, bf[ni].w);
            }
        }
        __syncthreads();
    }

#pragma unroll
    for (int mi = 0; mi < 4; mi++) {
        int r0 = rowBase + wm * 64 + mi * 16 + g;
#pragma unroll
        for (int ni = 0; ni < 4; ni++) {
            int cb = colBase + wn * 32 + ni * 8 + t4 * 2;
            float* a = acc[mi][ni];
#pragma unroll
            for (int half = 0; half < 2; half++) {
                int r = r0 + half * 8;
                if (r >= M) continue;
                size_t p = (size_t)r * N + cb;
                float v0 = a[half * 2], v1 = a[half * 2 + 1];
                if (gate != 0) {
                    float2 x = __half22float2(*(const half2*)(X + p));
                    v0 = sigmoidf_(v0 + bias[cb])     * x.x;
                    v1 = sigmoidf_(v1 + bias[cb + 1]) * x.y;
                    if (gate == 2) {
                        float2 y = __half22float2(*(const half2*)(Y + p));
                        v0 += y.x; v1 += y.y;
                    }
                }
                *(half2*)(C + p) = __floats2half2_rn(v0, v1);
            }
        }
    }
}

// ---------------- weight permute+convert pre-pass ------------------------
__global__ void permute_h(const float* __restrict__ in, __half2* __restrict__ out, int nWords)
{
    int i = blockIdx.x * blockDim.x + threadIdx.x;
    if (i >= nWords) return;
    int q = i & 15;
    int w = 4 * (q & 3) + (q >> 2);
    int k = ((i & ~15) << 1) + 2 * w;
    out[i] = __floats2half2_rn(in[k], in[k + 1]);
}

// ---------------- 512x512 transpose (+ permute + fp16) -------------------
__global__ void transpose512h(const float* __restrict__ in, __half* __restrict__ out)
{
    __shared__ float t[32][33];
    int x = blockIdx.x * 32 + threadIdx.x;
    int y0 = blockIdx.y * 32;
#pragma unroll
    for (int i = threadIdx.y; i < 32; i += 8)
        t[i][threadIdx.x] = in[(size_t)(y0 + i) * 512 + x];
    __syncthreads();
    int ox = blockIdx.y * 32 + threadIdx.x;
    int grp = ox >> 5, o = ox & 31, pr = o >> 1;
    int q = 4 * (pr & 3) + (pr >> 2);
    int pos = (grp << 5) + 2 * q + (o & 1);
    int oy0 = blockIdx.x * 32;
#pragma unroll
    for (int i = threadIdx.y; i < 32; i += 8)
        out[(size_t)(oy0 + i) * 512 + pos] = __float2half_rn(t[threadIdx.x][i]);
}

// ---------------- attention score reductions ----------------
__global__ void attn_scores8(const __half* __restrict__ z, const float* __restrict__ a,
                             float* __restrict__ ssrc, float* __restrict__ sdst, int n)
{
    int warp = (blockIdx.x * blockDim.x + threadIdx.x) >> 5;
    int lane = threadIdx.x & 31;
    if (warp >= n * HEADS) return;
    int node = warp >> 3, h = warp & 7;
    const __half* zr = z + (size_t)node * FUSEDD + h * HID;
    const float* ar = a + h * (2 * HID);
    float v0 = __half2float(zr[lane]), v1 = __half2float(zr[lane + 32]);
    float ss = v0 * ar[lane] + v1 * ar[lane + 32];
    float sd = v0 * ar[64 + lane] + v1 * ar[96 + lane];
#pragma unroll
    for (int d = 16; d; d >>= 1) {
        ss += __shfl_xor_sync(0xffffffffu, ss, d);
        sd += __shfl_xor_sync(0xffffffffu, sd, d);
    }
    if (lane == 0) { ssrc[warp] = ss; sdst[warp] = sd; }
}

__global__ void attn_scores1(const __half* __restrict__ z, const float* __restrict__ a,
                             float* __restrict__ ssrc, float* __restrict__ sdst, int n)
{
    int warp = (blockIdx.x * blockDim.x + threadIdx.x) >> 5;
    int lane = threadIdx.x & 31;
    if (warp >= n) return;
    const __half* zr = z + (size_t)warp * OUT_D;
    float ss = 0.f, sd = 0.f;
#pragma unroll
    for (int o = lane; o < OUT_D; o += 32) {
        float v = __half2float(zr[o]);
        ss += v * a[o];
        sd += v * a[OUT_D + o];
    }
#pragma unroll
    for (int d = 16; d; d >>= 1) {
        ss += __shfl_xor_sync(0xffffffffu, ss, d);
        sd += __shfl_xor_sync(0xffffffffu, sd, d);
    }
    if (lane == 0) { ssrc[warp] = ss; sdst[warp] = sd; }
}

// ---------------- per-layer init ----------------
__global__ void init_l1()
{
    int i = blockIdx.x * blockDim.x + threadIdx.x;
    if (i < N_DST0 * HEADS) g_den0[i] = 0.f;
    if (i < N_DST0) { g_cnt0[i] = 0; g_cur0[i] = 0; }
}
__global__ void init_l2()
{
    int i = blockIdx.x * blockDim.x + threadIdx.x;
    if (i < N_DST1) { g_den1[i] = 0.f; g_cnt1[i] = 0; g_cur1[i] = 0; }
}

// ---------------- edge softmax (max-free) + fused histogram --------------
// w stored fp16 (exp(v) of O(1) scores: far inside fp16 range)
template <int H>
__global__ void edge_exp(const int* __restrict__ src, const int* __restrict__ dst,
                         const float* __restrict__ ssrc, const float* __restrict__ sdst,
                         __half* __restrict__ w, float* __restrict__ den,
                         int* __restrict__ cnt, int E)
{
    int i = blockIdx.x * blockDim.x + threadIdx.x;
    if (i >= E * H) return;
    int e = i / H, h = i - e * H;
    int d = dst[e];
    float v = ssrc[src[e] * H + h] + sdst[d * H + h];
    v = v > 0.f ? v : 0.01f * v;
    float ex = __expf(v);
    w[i] = __float2half_rn(ex);
    atomicAdd(&den[d * H + h], ex);
    if (h == 0) atomicAdd(&cnt[d], 1);
}

// ---------------- CSR build ----------------
__global__ void exscan_k(const int* __restrict__ cnt, int* __restrict__ off, int n)
{
    __shared__ int sm[1024];
    int tid = threadIdx.x;
    int chunk = (n + 1023) >> 10;
    int s = tid * chunk;
    int e = s + chunk < n ? s + chunk : n;
    int sum = 0;
    for (int i = s; i < e; i++) sum += cnt[i];
    sm[tid] = sum;
    __syncthreads();
    for (int d = 1; d < 1024; d <<= 1) {
        int t = (tid >= d) ? sm[tid - d] : 0;
        __syncthreads();
        sm[tid] += t;
        __syncthreads();
    }
    int run = sm[tid] - sum;
    for (int i = s; i < e; i++) { off[i] = run; run += cnt[i]; }
    if (tid == 1023) off[n] = sm[1023];
}

__global__ void scatter_k(const int* __restrict__ dst, const int* __restrict__ off,
                          int* __restrict__ cur, int* __restrict__ sorted, int E)
{
    int i = blockIdx.x * blockDim.x + threadIdx.x;
    if (i >= E) return;
    int d = dst[i];
    int p = atomicAdd(&cur[d], 1);
    sorted[off[d] + p] = i;
}

// ---------------- aggregation ----------------
// layer 1: block per dst node; edge ids, src ids AND per-edge 8-head fp16
// weight vectors (uint4, 16B) staged through smem -> hot loop is pure
// smem-broadcast alpha + independent fp16 z gathers; fp32 accumulate;
// fused ELU; fp16 output (feeds z2 GEMM A).
__global__ __launch_bounds__(128) void aggregate8_elu(
    const int* __restrict__ sorted, const int* __restrict__ off,
    const int* __restrict__ esrc, const __half* __restrict__ w,
    const float* __restrict__ den, const __half* __restrict__ z,
    __half* __restrict__ out)
{
    __shared__ int s_src[128];
    __shared__ uint4 s_w4[128];
    int d = blockIdx.x;
    int t = threadIdx.x;
    int h = t >> 4;
    float4 acc = make_float4(0.f, 0.f, 0.f, 0.f);
    int s = off[d], e = off[d + 1];
    for (int base = s; base < e; base += 128) {
        int nch = min(128, e - base);
        __syncthreads();
        if (t < nch) {
            int ed = sorted[base + t];
            s_src[t] = esrc[ed];
            s_w4[t] = *(const uint4*)(w + (size_t)ed * HEADS);
        }
        __syncthreads();
#pragma unroll 4
        for (int j = 0; j < nch; j++) {
            float alpha = __half2float(((const __half*)&s_w4[j])[h]);
            uint2 u = *(const uint2*)(z + (size_t)s_src[j] * FUSEDD + t * 4);
            float2 f0 = __half22float2(*(const half2*)&u.x);
            float2 f1 = __half22float2(*(const half2*)&u.y);
            acc.x += alpha * f0.x;
            acc.y += alpha * f0.y;
            acc.z += alpha * f1.x;
            acc.w += alpha * f1.y;
        }
    }
    float inv = 1.f / den[d * HEADS + h];
    acc.x *= inv; acc.y *= inv; acc.z *= inv; acc.w *= inv;
    acc.x = acc.x > 0.f ? acc.x : (__expf(acc.x) - 1.f);
    acc.y = acc.y > 0.f ? acc.y : (__expf(acc.y) - 1.f);
    acc.z = acc.z > 0.f ? acc.z : (__expf(acc.z) - 1.f);
    acc.w = acc.w > 0.f ? acc.w : (__expf(acc.w) - 1.f);
    uint2 st;
    st.x = h2u(__floats2half2_rn(acc.x, acc.y));
    st.y = h2u(__floats2half2_rn(acc.z, acc.w));
    *(uint2*)(out + (size_t)d * FUSEDD + t * 4) = st;
}

__global__ __launch_bounds__(128) void aggregate1(
    const int* __restrict__ sorted, const int* __restrict__ off,
    const int* __restrict__ esrc, const __half* __restrict__ w,
    const float* __restrict__ den, const __half* __restrict__ z,
    float* __restrict__ out)
{
    __shared__ int s_src[128];
    __shared__ float s_w[128];
    int d = blockIdx.x;
    int c = threadIdx.x;
    float acc = 0.f;
    int s = off[d], e = off[d + 1];
    for (int base = s; base < e; base += 128) {
        int nch = min(128, e - base);
        __syncthreads();
        if (c < nch) {
            int ed = sorted[base + c];
            s_src[c] = esrc[ed];
            s_w[c] = __half2float(w[ed]);
        }
        __syncthreads();
#pragma unroll 4
        for (int j = 0; j < nch; j++)
            acc += s_w[j] * __half2float(z[(size_t)s_src[j] * OUT_D + c]);
    }
    out[(size_t)d * OUT_D + c] = acc / den[d];
}

// ---------------- host launcher ----------------
extern "C" void kernel_launch(void* const* d_in, const int* in_sizes, int n_in,
                              void* d_out, int out_size)
{
    (void)in_sizes; (void)n_in; (void)out_size;
    const float* img   = (const float*)d_in[0];
    const float* blk   = (const float*)d_in[1];
    const float* W_img = (const float*)d_in[2];
    const float* W_blk = (const float*)d_in[3];
    const float* Wv    = (const float*)d_in[4];
    const float* bv    = (const float*)d_in[5];
    const float* We    = (const float*)d_in[6];
    const float* be    = (const float*)d_in[7];
    const float* fc1   = (const float*)d_in[8];
    const float* attn1 = (const float*)d_in[9];
    const float* fc2   = (const float*)d_in[10];
    const float* attn2 = (const float*)d_in[11];
    const int* e0s = (const int*)d_in[12];
    const int* e0d = (const int*)d_in[13];
    const int* e1s = (const int*)d_in[14];
    const int* e1d = (const int*)d_in[15];
    float* out = (float*)d_out;

    float *fi, *ti, *c, *wT, *wBig;
    float *ssrc0, *sdst0, *den0, *w0;
    int *cnt0, *off0, *cur0, *sorted0;
    float *ssrc1, *sdst1, *den1, *w1;
    int *cnt1, *off1, *cur1, *sorted1;
    cudaGetSymbolAddress((void**)&fi, g_fi);
    cudaGetSymbolAddress((void**)&ti, g_ti);
    cudaGetSymbolAddress((void**)&c,  g_c);
    cudaGetSymbolAddress((void**)&wT, g_wT);
    cudaGetSymbolAddress((void**)&wBig, g_wBig);
    cudaGetSymbolAddress((void**)&ssrc0, g_ssrc0);
    cudaGetSymbolAddress((void**)&sdst0, g_sdst0);
    cudaGetSymbolAddress((void**)&den0, g_den0);
    cudaGetSymbolAddress((void**)&w0, g_w0);
    cudaGetSymbolAddress((void**)&cnt0, g_cnt0);
    cudaGetSymbolAddress((void**)&off0, g_off0);
    cudaGetSymbolAddress((void**)&cur0, g_cur0);
    cudaGetSymbolAddress((void**)&sorted0, g_sorted0);
    cudaGetSymbolAddress((void**)&ssrc1, g_ssrc1);
    cudaGetSymbolAddress((void**)&sdst1, g_sdst1);
    cudaGetSymbolAddress((void**)&den1, g_den1);
    cudaGetSymbolAddress((void**)&w1, g_w1);
    cudaGetSymbolAddress((void**)&cnt1, g_cnt1);
    cudaGetSymbolAddress((void**)&off1, g_off1);
    cudaGetSymbolAddress((void**)&cur1, g_cur1);
    cudaGetSymbolAddress((void**)&sorted1, g_sorted1);

    __half* fiH = (__half*)fi;
    __half* tiH = (__half*)ti;
    __half* cH  = (__half*)c;
    __half* wTH = (__half*)wT;
    __half* wBigH = (__half*)wBig;
    __half* w0H = (__half*)w0;
    __half* w1H = (__half*)w1;

    dim3 tb(256);
    dim3 gBig(FUSEDD / BN, (N_SRC0 + BM - 1) / BM);

    // 1: projection 1 (A = img fp32, converted in staging)
    permute_h<<<(FUSEDD * IMG_D / 2 + 255) / 256, tb>>>(W_img, (__half2*)wBigH, FUSEDD * IMG_D / 2);
    gemm_hc<false><<<gBig, tb>>>(img, wBigH, fiH, N_SRC0, FUSEDD, IMG_D, 0, nullptr, nullptr, nullptr);

    // 2: projection 2
    permute_h<<<(FUSEDD * BLK_D / 2 + 255) / 256, tb>>>(W_blk, (__half2*)wBigH, FUSEDD * BLK_D / 2);
    gemm_hc<false><<<gBig, tb>>>(blk, wBigH, tiH, N_SRC0, FUSEDD, BLK_D, 0, nullptr, nullptr, nullptr);

    // 3: visual gate fused: c = sigmoid(fi@Wv + bv) * fi
    transpose512h<<<dim3(16, 16), dim3(32, 8)>>>(Wv, wTH);
    gemm_hc<true><<<gBig, tb>>>(fiH, wTH, cH, N_SRC0, FUSEDD, FUSEDD, 1, bv, fiH, nullptr);

    // 4: edge gate fused: c = sigmoid(ti@We + be) * ti + c  (c = fused)
    transpose512h<<<dim3(16, 16), dim3(32, 8)>>>(We, wTH);
    gemm_hc<true><<<gBig, tb>>>(tiH, wTH, cH, N_SRC0, FUSEDD, FUSEDD, 2, be, tiH, cH);

    // 5: z1 = fused @ fc1^T -> tiH
    permute_h<<<(FUSEDD * FUSEDD / 2 + 255) / 256, tb>>>(fc1, (__half2*)wBigH, FUSEDD * FUSEDD / 2);
    gemm_hc<true><<<gBig, tb>>>(cH, wBigH, tiH, N_SRC0, FUSEDD, FUSEDD, 0, nullptr, nullptr, nullptr);

    // 6: attention scores layer 1
    attn_scores8<<<(N_SRC0 * HEADS * 32 + 255) / 256, tb>>>(tiH, attn1, ssrc0, sdst0, N_SRC0);

    // 7-11: edge softmax (+fused hist) + CSR + aggregate -> fiH (h1)
    init_l1<<<(N_DST0 * HEADS + 255) / 256, tb>>>();
    edge_exp<HEADS><<<(E0 * HEADS + 255) / 256, tb>>>(e0s, e0d, ssrc0, sdst0, w0H, den0, cnt0, E0);
    exscan_k<<<1, 1024>>>(cnt0, off0, N_DST0);
    scatter_k<<<(E0 + 255) / 256, tb>>>(e0d, off0, cur0, sorted0, E0);
    aggregate8_elu<<<N_DST0, 128>>>(sorted0, off0, e0s, w0H, den0, tiH, fiH);

    // 12: z2 = h1 @ fc2^T -> cH
    permute_h<<<(OUT_D * FUSEDD / 2 + 255) / 256, tb>>>(fc2, (__half2*)wBigH, OUT_D * FUSEDD / 2);
    gemm_hc<true><<<dim3(OUT_D / BN, (N_SRC1 + BM - 1) / BM), tb>>>(fiH, wBigH, cH, N_SRC1, OUT_D, FUSEDD, 0, nullptr, nullptr, nullptr);

    // 13-17: layer 2 edge softmax + aggregate -> d_out (fp32)
    attn_scores1<<<(N_SRC1 * 32 + 255) / 256, tb>>>(cH, attn2, ssrc1, sdst1, N_SRC1);
    init_l2<<<(N_DST1 + 255) / 256, tb>>>();
    edge_exp<1><<<(E1 + 255) / 256, tb>>>(e1s, e1d, ssrc1, sdst1, w1H, den1, cnt1, E1);
    exscan_k<<<1, 1024>>>(cnt1, off1, N_DST1);
    scatter_k<<<(E1 + 255) / 256, tb>>>(e1d, off1, cur1, sorted1, E1);
    aggregate1<<<N_DST1, 128>>>(sorted1, off1, e1s, w1H, den1, cH, out);
}